// round 10
// baseline (speedup 1.0000x reference)
#include <cuda_runtime.h>
#include <cuda_bf16.h>
#include <math.h>
#include <stdint.h>

// ---------------- problem constants ----------------
#define BB   16
#define NN   4096
#define SS   512
#define DD2  384
#define KNN  5
#define MM   (BB*NN)          // 65536 rows
#define KPAD 416              // padded K stride (bf16 arrays), 13*32, covers 387
#define OC   384              // output channels
#define X_ELEMS ((size_t)MM*DD2)   // 25165824
#define EPSF 1.1920929e-7f

// K-order permutation: k 0..383 = interpolated feature k, k 384..386 = xyz, 387.. = 0.
// Weights permuted identically, so the GEMM result is unchanged.

// ---------------- device scratch (static, no allocation) ----------------
__device__ __align__(128) __nv_bfloat16 g_Ah[(size_t)MM * KPAD];
__device__ __align__(128) __nv_bfloat16 g_Al[(size_t)MM * KPAD];
__device__ __align__(128) float g_X0[(size_t)MM * DD2];
__device__ __align__(128) __nv_bfloat16 g_W0h[OC * KPAD];
__device__ __align__(128) __nv_bfloat16 g_W0l[OC * KPAD];
__device__ __align__(128) __nv_bfloat16 g_W1h[OC * KPAD];
__device__ __align__(128) __nv_bfloat16 g_W1l[OC * KPAD];
__device__ int   g_idx[MM * KNN];
__device__ float g_w[MM * KNN];
__device__ float g_part[512 * 2 * DD2];
__device__ float g_scale[2 * DD2];
__device__ float g_shift[2 * DD2];

// ---------------- helpers ----------------
__device__ __forceinline__ uint32_t smem_u32(const void* p) {
    uint32_t a;
    asm("{ .reg .u64 t; cvta.to.shared.u64 t, %1; cvt.u32.u64 %0, t; }" : "=r"(a) : "l"(p));
    return a;
}
__device__ __forceinline__ void cp16(uint32_t s, const void* g) {
    asm volatile("cp.async.cg.shared.global [%0], [%1], 16;" :: "r"(s), "l"(g));
}
#define CP_COMMIT() asm volatile("cp.async.commit_group;")
#define CP_WAIT1()  asm volatile("cp.async.wait_group 1;")
#define CP_WAIT0()  asm volatile("cp.async.wait_group 0;")

#define LDSM4(r, addr) \
    asm volatile("ldmatrix.sync.aligned.m8n8.x4.shared.b16 {%0,%1,%2,%3}, [%4];" \
        : "=r"((r)[0]), "=r"((r)[1]), "=r"((r)[2]), "=r"((r)[3]) : "r"(addr))

__device__ __forceinline__ void mma16816(float* c, const uint32_t* a, const uint32_t* b) {
    asm volatile(
        "mma.sync.aligned.m16n8k16.row.col.f32.bf16.bf16.f32 "
        "{%0,%1,%2,%3}, {%4,%5,%6,%7}, {%8,%9}, {%0,%1,%2,%3};"
        : "+f"(c[0]), "+f"(c[1]), "+f"(c[2]), "+f"(c[3])
        : "r"(a[0]), "r"(a[1]), "r"(a[2]), "r"(a[3]), "r"(b[0]), "r"(b[1]));
}

__device__ __forceinline__ float gelu_exact(float v) {
    return 0.5f * v * (1.0f + erff(v * 0.7071067811865476f));
}
__device__ __forceinline__ void split_bf16(float v, __nv_bfloat16 &h, __nv_bfloat16 &l) {
    h = __float2bfloat16(v);
    l = __float2bfloat16(v - __bfloat162float(h));
}

// ---------------- weight prep: permute + split + pad ----------------
__global__ void prep_weights_kernel(const float* __restrict__ W0,
                                    const float* __restrict__ W1) {
    int i = blockIdx.x * blockDim.x + threadIdx.x;
    if (i >= OC * KPAD) return;
    int o = i / KPAD, k = i % KPAD;
    float v0 = 0.0f, v1 = 0.0f;
    if (k < 384)      v0 = W0[o * 387 + 3 + k];     // feature part
    else if (k < 387) v0 = W0[o * 387 + (k - 384)]; // xyz part
    if (k < 384)      v1 = W1[o * 384 + k];
    __nv_bfloat16 h, l;
    split_bf16(v0, h, l); g_W0h[i] = h; g_W0l[i] = l;
    split_bf16(v1, h, l); g_W1h[i] = h; g_W1l[i] = l;
}

// ---------------- KNN (3-FFMA comparison key) ----------------
__global__ void knn_kernel(const float* __restrict__ xyz1,
                           const float* __restrict__ xyz2,
                           const int* __restrict__ elens,
                           float* __restrict__ out_idx) {
    __shared__ float4 sk[SS];
    int b = blockIdx.y;
    const float* x2 = xyz2 + (size_t)b * SS * 3;
    for (int i = threadIdx.x; i < SS; i += blockDim.x) {
        float x = x2[i * 3 + 0], y = x2[i * 3 + 1], z = x2[i * 3 + 2];
        float ss = __fmaf_rn(z, z, __fmaf_rn(y, y, x * x));
        sk[i] = make_float4(-2.0f * x, -2.0f * y, -2.0f * z, ss);
    }
    __syncthreads();
    int n = blockIdx.x * blockDim.x + threadIdx.x;
    int row = b * NN + n;
    float px = xyz1[(size_t)row * 3 + 0];
    float py = xyz1[(size_t)row * 3 + 1];
    float pz = xyz1[(size_t)row * 3 + 2];
    int sv = elens[b];
    // d' = d2 - |p|^2 : same ordering as d2 for a fixed query
    float b0 = 1e30f, b1 = 1e30f, b2 = 1e30f, b3 = 1e30f, b4 = 1e30f;
    int j0 = 0, j1 = 0, j2 = 0, j3 = 0, j4 = 0;
    for (int s = 0; s < sv; ++s) {
        float4 q = sk[s];
        float d = __fmaf_rn(px, q.x, __fmaf_rn(py, q.y, __fmaf_rn(pz, q.z, q.w)));
        if (d < b4) {
            if (d < b3) {
                b4 = b3; j4 = j3;
                if (d < b2) {
                    b3 = b2; j3 = j2;
                    if (d < b1) {
                        b2 = b1; j2 = j1;
                        if (d < b0) { b1 = b0; j1 = j0; b0 = d; j0 = s; }
                        else        { b1 = d;  j1 = s; }
                    } else { b2 = d; j2 = s; }
                } else { b3 = d; j3 = s; }
            } else { b4 = d; j4 = s; }
        }
    }
    // recompute true squared distances for the 5 winners
    int js[5] = { j0, j1, j2, j3, j4 };
    float rr[5];
#pragma unroll
    for (int t = 0; t < 5; ++t) {
        float4 q = sk[js[t]];
        float sx = -0.5f * q.x, sy = -0.5f * q.y, sz = -0.5f * q.z;
        float dx = px - sx, dy = py - sy, dz = pz - sz;
        float d2 = __fmaf_rn(dz, dz, __fmaf_rn(dy, dy, dx * dx));
        rr[t] = 1.0f / (d2 + EPSF);
    }
    float rsum = ((((rr[0] + rr[1]) + rr[2]) + rr[3]) + rr[4]);
    size_t base = (size_t)row * KNN;
#pragma unroll
    for (int t = 0; t < 5; ++t) {
        g_idx[base + t] = js[t];
        g_w[base + t] = rr[t] / rsum;
        out_idx[base + t] = (float)js[t];
    }
}

// ---------------- interp: smem-tiled gather -> g_Ah/g_Al -----------------
// grid (6 chunks, 16 batches); block 256. Each block stages
// points2[b][:, ch0:ch0+64] (512x64 f32 = 128 KB) in smem, then processes
// all 4096 rows: lane handles 2 adjacent channels -> bf16x2 stores.
#define INTERP_SMEM (SS * 64 * 4)
__global__ __launch_bounds__(256)
void interp_tile_kernel(const float* __restrict__ points2) {
    extern __shared__ float sP[];   // [512][64]
    int b = blockIdx.y;
    int ch0 = blockIdx.x * 64;
    int tid = threadIdx.x, lane = tid & 31, wid = tid >> 5;

    const float* p2 = points2 + (size_t)b * SS * DD2 + ch0;
    for (int i = tid; i < SS * 16; i += 256) {
        int s = i >> 4, q = i & 15;
        *(float4*)&sP[s * 64 + q * 4] = *(const float4*)(p2 + (size_t)s * DD2 + q * 4);
    }
    __syncthreads();

    // each warp: rows wid, wid+8, ...
    for (int n = wid; n < NN; n += 8) {
        int row = b * NN + n;
        size_t base = (size_t)row * KNN;
        int i0 = __ldg(&g_idx[base + 0]);
        int i1 = __ldg(&g_idx[base + 1]);
        int i2 = __ldg(&g_idx[base + 2]);
        int i3 = __ldg(&g_idx[base + 3]);
        int i4 = __ldg(&g_idx[base + 4]);
        float w0 = __ldg(&g_w[base + 0]);
        float w1 = __ldg(&g_w[base + 1]);
        float w2 = __ldg(&g_w[base + 2]);
        float w3 = __ldg(&g_w[base + 3]);
        float w4 = __ldg(&g_w[base + 4]);
        int c = 2 * lane;   // channel pair within chunk
        float2 v0 = *(const float2*)&sP[i0 * 64 + c];
        float2 v1 = *(const float2*)&sP[i1 * 64 + c];
        float2 v2 = *(const float2*)&sP[i2 * 64 + c];
        float2 v3 = *(const float2*)&sP[i3 * 64 + c];
        float2 v4 = *(const float2*)&sP[i4 * 64 + c];
        float ax = w0 * v0.x; ax = __fmaf_rn(w1, v1.x, ax); ax = __fmaf_rn(w2, v2.x, ax);
        ax = __fmaf_rn(w3, v3.x, ax); ax = __fmaf_rn(w4, v4.x, ax);
        float ay = w0 * v0.y; ay = __fmaf_rn(w1, v1.y, ay); ay = __fmaf_rn(w2, v2.y, ay);
        ay = __fmaf_rn(w3, v3.y, ay); ay = __fmaf_rn(w4, v4.y, ay);
        __nv_bfloat16 hx, lx, hy, ly;
        split_bf16(ax, hx, lx); split_bf16(ay, hy, ly);
        size_t o = (size_t)row * KPAD + ch0 + c;
        *(__nv_bfloat162*)(g_Ah + o) = __nv_bfloat162{hx, hy};
        *(__nv_bfloat162*)(g_Al + o) = __nv_bfloat162{lx, ly};
    }
}

// ---------------- pad kernel: xyz cols (384..386) + zeros (387..415) -----
__global__ void pad_xyz_kernel(const float* __restrict__ points1) {
    // one thread per (row, bf16x2 pair i in 0..15) covering cols 384..415
    int g = blockIdx.x * blockDim.x + threadIdx.x;
    if (g >= MM * 16) return;
    int row = g >> 4, i = g & 15;
    int col = 384 + 2 * i;
    float vx = 0.0f, vy = 0.0f;
    if (col == 384) { vx = points1[(size_t)row * 3 + 0]; vy = points1[(size_t)row * 3 + 1]; }
    else if (col == 386) { vx = points1[(size_t)row * 3 + 2]; vy = 0.0f; }
    __nv_bfloat16 hx, lx, hy, ly;
    split_bf16(vx, hx, lx); split_bf16(vy, hy, ly);
    size_t o = (size_t)row * KPAD + col;
    *(__nv_bfloat162*)(g_Ah + o) = __nv_bfloat162{hx, hy};
    *(__nv_bfloat162*)(g_Al + o) = __nv_bfloat162{lx, ly};
}

// ---------------- bf16x3 GEMM via mma.sync + fused masked stats ----------
// C[M,384] = A[M,nk] * B^T.  CTA tile 128x128, warp 64x32, KC=32, 2 stages.
// (R7 configuration — measured fastest.)
#define STAGE_SZ 32768
#define GEMM_SMEM (2*STAGE_SZ)

__global__ __launch_bounds__(256, 2)
void gemm_mma_kernel(const __nv_bfloat16* __restrict__ Ahp,
                     const __nv_bfloat16* __restrict__ Alp,
                     const __nv_bfloat16* __restrict__ Bhp,
                     const __nv_bfloat16* __restrict__ Blp,
                     float* __restrict__ X, int nk,
                     const int* __restrict__ plens) {
    extern __shared__ __align__(128) char smem[];
    uint32_t sb = smem_u32(smem);
    int tid = threadIdx.x, lane = tid & 31, wid = tid >> 5;
    int wm = wid & 1, wn = wid >> 1;
    int mbase = blockIdx.y * 128, nbase = blockIdx.x * 128;
    int nst = nk >> 5;

    int lrow = tid >> 2, lc = tid & 3;

    auto load_stage = [&](int st) {
        uint32_t sA = sb + (st & 1) * STAGE_SZ;
        int kb = st * 32;
#pragma unroll
        for (int i = 0; i < 2; ++i) {
            int row = lrow + i * 64;
            uint32_t so = row * 64 + ((uint32_t)(lc ^ ((row >> 1) & 3)) << 4);
            size_t ga = (size_t)(mbase + row) * KPAD + kb + lc * 8;
            size_t gb = (size_t)(nbase + row) * KPAD + kb + lc * 8;
            cp16(sA + so,         Ahp + ga);
            cp16(sA + 8192 + so,  Alp + ga);
            cp16(sA + 16384 + so, Bhp + gb);
            cp16(sA + 24576 + so, Blp + gb);
        }
    };

    float acc[4][4][4] = {};

    load_stage(0); CP_COMMIT();

    int arow = lane & 15;            // A: row within m16 tile
    int ahalf = lane >> 4;           // A: k-chunk half
    int brow = (lane & 7) + ((lane >> 4) << 3);  // B: n within 16
    int bhalf = (lane >> 3) & 1;     // B: k-chunk half

    for (int st = 0; st < nst; ++st) {
        if (st + 1 < nst) { load_stage(st + 1); CP_COMMIT(); CP_WAIT1(); }
        else              { CP_WAIT0(); }
        __syncthreads();
        uint32_t sA = sb + (st & 1) * STAGE_SZ;
        uint32_t sAl = sA + 8192, sB = sA + 16384, sBl = sA + 24576;
#pragma unroll
        for (int k2 = 0; k2 < 2; ++k2) {
            int cbase = 2 * k2;
            uint32_t ah[4][4], bh[2][4], bl[2][4];
            uint32_t aso[4], bso[2];
#pragma unroll
            for (int mi = 0; mi < 4; ++mi) {
                int row = wm * 64 + mi * 16 + arow;
                aso[mi] = row * 64 + ((uint32_t)((cbase + ahalf) ^ ((row >> 1) & 3)) << 4);
                LDSM4(ah[mi], sA + aso[mi]);
            }
#pragma unroll
            for (int g = 0; g < 2; ++g) {
                int row = wn * 32 + g * 16 + brow;
                bso[g] = row * 64 + ((uint32_t)((cbase + bhalf) ^ ((row >> 1) & 3)) << 4);
                LDSM4(bh[g], sB + bso[g]);
            }
            // A_hi * B_hi
#pragma unroll
            for (int mi = 0; mi < 4; ++mi)
#pragma unroll
                for (int ni = 0; ni < 4; ++ni)
                    mma16816(acc[mi][ni], ah[mi], &bh[ni >> 1][(ni & 1) * 2]);
            // A_hi * B_lo
#pragma unroll
            for (int g = 0; g < 2; ++g) LDSM4(bl[g], sBl + bso[g]);
#pragma unroll
            for (int mi = 0; mi < 4; ++mi)
#pragma unroll
                for (int ni = 0; ni < 4; ++ni)
                    mma16816(acc[mi][ni], ah[mi], &bl[ni >> 1][(ni & 1) * 2]);
            // A_lo * B_hi  (reuse ah registers for A_lo)
#pragma unroll
            for (int mi = 0; mi < 4; ++mi) LDSM4(ah[mi], sAl + aso[mi]);
#pragma unroll
            for (int mi = 0; mi < 4; ++mi)
#pragma unroll
                for (int ni = 0; ni < 4; ++ni)
                    mma16816(acc[mi][ni], ah[mi], &bh[ni >> 1][(ni & 1) * 2]);
        }
        __syncthreads();
    }

    // ---- output store ----
    int row0 = mbase + wm * 64 + (lane >> 2);
    int col0 = nbase + wn * 32 + 2 * (lane & 3);
#pragma unroll
    for (int mi = 0; mi < 4; ++mi) {
#pragma unroll
        for (int ni = 0; ni < 4; ++ni) {
            int r = row0 + mi * 16;
            int c = col0 + ni * 8;
            float2 v;
            v.x = acc[mi][ni][0]; v.y = acc[mi][ni][1];
            *(float2*)(X + (size_t)r * OC + c) = v;
            v.x = acc[mi][ni][2]; v.y = acc[mi][ni][3];
            *(float2*)(X + (size_t)(r + 8) * OC + c) = v;
        }
    }

    // ---- fused masked stats: per-column sum / sumsq for this 128-row chunk ----
    float* sbuf = (float*)smem;     // 256 floats: [0..127]=sum, [128..255]=sumsq
    __syncthreads();                // mainloop smem reads done, reuse buffer
    sbuf[tid] = 0.0f;
    __syncthreads();

    int bidx = mbase >> 12;
    int lim = plens[bidx] - (mbase & 4095);
    int nv = lim < 0 ? 0 : (lim > 128 ? 128 : lim);
    int ritb = wm * 64 + (lane >> 2);

    float csum[8], csq[8];
#pragma unroll
    for (int t = 0; t < 8; ++t) { csum[t] = 0.0f; csq[t] = 0.0f; }
#pragma unroll
    for (int mi = 0; mi < 4; ++mi) {
#pragma unroll
        for (int j = 0; j < 2; ++j) {
            bool v = (ritb + mi * 16 + 8 * j) < nv;
            if (v) {
#pragma unroll
                for (int ni = 0; ni < 4; ++ni) {
                    float a0 = acc[mi][ni][2 * j + 0];
                    float a1 = acc[mi][ni][2 * j + 1];
                    csum[2 * ni + 0] += a0;
                    csq[2 * ni + 0] = __fmaf_rn(a0, a0, csq[2 * ni + 0]);
                    csum[2 * ni + 1] += a1;
                    csq[2 * ni + 1] = __fmaf_rn(a1, a1, csq[2 * ni + 1]);
                }
            }
        }
    }
#pragma unroll
    for (int m = 4; m <= 16; m <<= 1) {
#pragma unroll
        for (int t = 0; t < 8; ++t) {
            csum[t] += __shfl_xor_sync(0xFFFFFFFFu, csum[t], m);
            csq[t]  += __shfl_xor_sync(0xFFFFFFFFu, csq[t], m);
        }
    }
    if (lane < 4) {
#pragma unroll
        for (int ni = 0; ni < 4; ++ni) {
#pragma unroll
            for (int j = 0; j < 2; ++j) {
                int col = wn * 32 + ni * 8 + 2 * lane + j;
                atomicAdd(&sbuf[col], csum[2 * ni + j]);
                atomicAdd(&sbuf[128 + col], csq[2 * ni + j]);
            }
        }
    }
    __syncthreads();
    int chunk = blockIdx.y;
    if (tid < 128)       g_part[(size_t)chunk * 768 + nbase + tid] = sbuf[tid];
    else                 g_part[(size_t)chunk * 768 + 384 + nbase + (tid - 128)] = sbuf[tid];
}

// ---------------- finalize: mean/var -> scale/shift ----------------------
__global__ void finalize_kernel(const float* __restrict__ gamma,
                                const float* __restrict__ beta,
                                const int* __restrict__ plens, int layer) {
    int c = blockIdx.x;    // 384 blocks
    int t = threadIdx.x;   // 128 threads
    float s = 0.0f, s2 = 0.0f;
    for (int i = t; i < 512; i += 128) {
        s  += g_part[(size_t)i * 768 + c];
        s2 += g_part[(size_t)i * 768 + 384 + c];
    }
    __shared__ float bs[128], bs2[128];
    bs[t] = s; bs2[t] = s2;
    __syncthreads();
    for (int o = 64; o > 0; o >>= 1) {
        if (t < o) { bs[t] += bs[t + o]; bs2[t] += bs2[t + o]; }
        __syncthreads();
    }
    if (t == 0) {
        float nf = 0.0f;
        for (int b = 0; b < BB; ++b) nf += (float)plens[b];
        nf = fmaxf(nf, 1.0f);
        float mean = bs[0] / nf;
        float var = bs2[0] / nf - mean * mean;
        var = fmaxf(var, 0.0f);
        float rs = rsqrtf(var + 1e-5f);
        float sc = gamma[c] * rs;
        g_scale[layer * DD2 + c] = sc;
        g_shift[layer * DD2 + c] = beta[c] - mean * sc;
    }
}

// ---------------- BN+GELU -> bf16 split activations ----------------------
__global__ void bn_gelu_split_kernel(const float* __restrict__ Xp,
                                     const int* __restrict__ plens) {
    size_t i4 = ((size_t)blockIdx.x * blockDim.x + threadIdx.x) * 4;
    if (i4 >= X_ELEMS) return;
    int row = (int)(i4 / DD2);
    int c = (int)(i4 % DD2);
    bool valid = (row & 4095) < plens[row >> 12];
    const float* sc = g_scale + c;
    const float* sh = g_shift + c;
    float4 x = *(const float4*)(Xp + i4);
    float y0 = 0.f, y1 = 0.f, y2 = 0.f, y3 = 0.f;
    if (valid) {
        y0 = gelu_exact(__fmaf_rn(x.x, sc[0], sh[0]));
        y1 = gelu_exact(__fmaf_rn(x.y, sc[1], sh[1]));
        y2 = gelu_exact(__fmaf_rn(x.z, sc[2], sh[2]));
        y3 = gelu_exact(__fmaf_rn(x.w, sc[3], sh[3]));
    }
    __nv_bfloat16 h0, l0, h1, l1, h2, l2, h3, l3;
    split_bf16(y0, h0, l0); split_bf16(y1, h1, l1);
    split_bf16(y2, h2, l2); split_bf16(y3, h3, l3);
    size_t o = (size_t)row * KPAD + c;
    __nv_bfloat162* ph = (__nv_bfloat162*)(g_Ah + o);
    __nv_bfloat162* pl = (__nv_bfloat162*)(g_Al + o);
    ph[0] = __nv_bfloat162{h0, h1}; ph[1] = __nv_bfloat162{h2, h3};
    pl[0] = __nv_bfloat162{l0, l1}; pl[1] = __nv_bfloat162{l2, l3};
}

// ---------------- final masked BN (fp32, in place) -----------------------
__global__ void bn_final_kernel(float* __restrict__ Y,
                                const int* __restrict__ plens) {
    size_t i4 = ((size_t)blockIdx.x * blockDim.x + threadIdx.x) * 4;
    if (i4 >= X_ELEMS) return;
    int row = (int)(i4 / DD2);
    int c = (int)(i4 % DD2);
    bool valid = (row & 4095) < plens[row >> 12];
    const float* sc = g_scale + DD2 + c;
    const float* sh = g_shift + DD2 + c;
    float4 x = *(const float4*)(Y + i4);
    float4 y;
    if (valid) {
        y.x = __fmaf_rn(x.x, sc[0], sh[0]);
        y.y = __fmaf_rn(x.y, sc[1], sh[1]);
        y.z = __fmaf_rn(x.z, sc[2], sh[2]);
        y.w = __fmaf_rn(x.w, sc[3], sh[3]);
    } else {
        y.x = y.y = y.z = y.w = 0.0f;
    }
    *(float4*)(Y + i4) = y;
}

// ---------------- launch ----------------
extern "C" void kernel_launch(void* const* d_in, const int* in_sizes, int n_in,
                              void* d_out, int out_size) {
    const float* xyz1    = (const float*)d_in[0];
    const float* xyz2    = (const float*)d_in[1];
    const float* points1 = (const float*)d_in[2];
    const float* points2 = (const float*)d_in[3];
    const int*   plens   = (const int*)d_in[4];
    const int*   elens   = (const int*)d_in[5];
    const float* W0 = (const float*)d_in[7];
    const float* g0 = (const float*)d_in[8];
    const float* b0 = (const float*)d_in[9];
    const float* W1 = (const float*)d_in[10];
    const float* g1 = (const float*)d_in[11];
    const float* b1 = (const float*)d_in[12];
    float* out = (float*)d_out;

    __nv_bfloat16 *pAh, *pAl, *pW0h, *pW0l, *pW1h, *pW1l;
    float* pX0;
    cudaGetSymbolAddress((void**)&pAh, g_Ah);
    cudaGetSymbolAddress((void**)&pAl, g_Al);
    cudaGetSymbolAddress((void**)&pX0, g_X0);
    cudaGetSymbolAddress((void**)&pW0h, g_W0h);
    cudaGetSymbolAddress((void**)&pW0l, g_W0l);
    cudaGetSymbolAddress((void**)&pW1h, g_W1h);
    cudaGetSymbolAddress((void**)&pW1l, g_W1l);

    cudaFuncSetAttribute(gemm_mma_kernel,
                         cudaFuncAttributeMaxDynamicSharedMemorySize, GEMM_SMEM);
    cudaFuncSetAttribute(interp_tile_kernel,
                         cudaFuncAttributeMaxDynamicSharedMemorySize, INTERP_SMEM);

    prep_weights_kernel<<<(OC * KPAD + 255) / 256, 256>>>(W0, W1);
    knn_kernel<<<dim3(NN / 256, BB), 256>>>(xyz1, xyz2, elens, out + X_ELEMS);
    pad_xyz_kernel<<<(MM * 16 + 255) / 256, 256>>>(points1);
    interp_tile_kernel<<<dim3(6, BB), 256, INTERP_SMEM>>>(points2);

    // layer 0: X0 = new_points @ W0^T  (K = 416 padded), stats fused
    gemm_mma_kernel<<<dim3(3, MM / 128), 256, GEMM_SMEM>>>(pAh, pAl, pW0h, pW0l, pX0, 416, plens);
    finalize_kernel<<<384, 128>>>(g0, b0, plens, 0);
    bn_gelu_split_kernel<<<(unsigned)(X_ELEMS / 4 + 255) / 256, 256>>>(pX0, plens);

    // layer 1: out = act @ W1^T  (K = 384), stats fused
    gemm_mma_kernel<<<dim3(3, MM / 128), 256, GEMM_SMEM>>>(pAh, pAl, pW1h, pW1l, out, 384, plens);
    finalize_kernel<<<384, 128>>>(g1, b1, plens, 1);
    bn_final_kernel<<<(unsigned)(X_ELEMS / 4 + 255) / 256, 256>>>(out, plens);
}

// round 11
// speedup vs baseline: 1.3261x; 1.3261x over previous
#include <cuda_runtime.h>
#include <cuda_bf16.h>
#include <math.h>
#include <stdint.h>

// ---------------- problem constants ----------------
#define BB   16
#define NN   4096
#define SS   512
#define DD2  384
#define KNN  5
#define MM   (BB*NN)          // 65536 rows
#define KPAD 416              // padded K stride (bf16 arrays), 13*32, covers 387
#define OC   384              // output channels
#define X_ELEMS ((size_t)MM*DD2)   // 25165824
#define EPSF 1.1920929e-7f

// K-order permutation: k 0..383 = interpolated feature k, k 384..386 = xyz, 387.. = 0.
// Weights permuted identically, so the GEMM result is unchanged.

// ---------------- device scratch (static, no allocation) ----------------
__device__ __align__(128) __nv_bfloat16 g_Ah[(size_t)MM * KPAD];
__device__ __align__(128) __nv_bfloat16 g_Al[(size_t)MM * KPAD];
__device__ __align__(128) float g_X0[(size_t)MM * DD2];
__device__ __align__(128) __nv_bfloat16 g_W0h[OC * KPAD];
__device__ __align__(128) __nv_bfloat16 g_W0l[OC * KPAD];
__device__ __align__(128) __nv_bfloat16 g_W1h[OC * KPAD];
__device__ __align__(128) __nv_bfloat16 g_W1l[OC * KPAD];
__device__ int   g_idx[MM * KNN];
__device__ float g_w[MM * KNN];
__device__ float g_part[512 * 2 * DD2];
__device__ float g_scale[2 * DD2];
__device__ float g_shift[2 * DD2];

// ---------------- helpers ----------------
__device__ __forceinline__ uint32_t smem_u32(const void* p) {
    uint32_t a;
    asm("{ .reg .u64 t; cvta.to.shared.u64 t, %1; cvt.u32.u64 %0, t; }" : "=r"(a) : "l"(p));
    return a;
}
__device__ __forceinline__ void cp16(uint32_t s, const void* g) {
    asm volatile("cp.async.cg.shared.global [%0], [%1], 16;" :: "r"(s), "l"(g));
}
#define CP_COMMIT() asm volatile("cp.async.commit_group;")
#define CP_WAIT1()  asm volatile("cp.async.wait_group 1;")
#define CP_WAIT0()  asm volatile("cp.async.wait_group 0;")

#define LDSM4(r, addr) \
    asm volatile("ldmatrix.sync.aligned.m8n8.x4.shared.b16 {%0,%1,%2,%3}, [%4];" \
        : "=r"((r)[0]), "=r"((r)[1]), "=r"((r)[2]), "=r"((r)[3]) : "r"(addr))

__device__ __forceinline__ void mma16816(float* c, const uint32_t* a, const uint32_t* b) {
    asm volatile(
        "mma.sync.aligned.m16n8k16.row.col.f32.bf16.bf16.f32 "
        "{%0,%1,%2,%3}, {%4,%5,%6,%7}, {%8,%9}, {%0,%1,%2,%3};"
        : "+f"(c[0]), "+f"(c[1]), "+f"(c[2]), "+f"(c[3])
        : "r"(a[0]), "r"(a[1]), "r"(a[2]), "r"(a[3]), "r"(b[0]), "r"(b[1]));
}

__device__ __forceinline__ float gelu_exact(float v) {
    return 0.5f * v * (1.0f + erff(v * 0.7071067811865476f));
}
__device__ __forceinline__ void split_bf16(float v, __nv_bfloat16 &h, __nv_bfloat16 &l) {
    h = __float2bfloat16(v);
    l = __float2bfloat16(v - __bfloat162float(h));
}

// ---------------- weight prep: permute + split + pad ----------------
__global__ void prep_weights_kernel(const float* __restrict__ W0,
                                    const float* __restrict__ W1) {
    int i = blockIdx.x * blockDim.x + threadIdx.x;
    if (i >= OC * KPAD) return;
    int o = i / KPAD, k = i % KPAD;
    float v0 = 0.0f, v1 = 0.0f;
    if (k < 384)      v0 = W0[o * 387 + 3 + k];     // feature part
    else if (k < 387) v0 = W0[o * 387 + (k - 384)]; // xyz part
    if (k < 384)      v1 = W1[o * 384 + k];
    __nv_bfloat16 h, l;
    split_bf16(v0, h, l); g_W0h[i] = h; g_W0l[i] = l;
    split_bf16(v1, h, l); g_W1h[i] = h; g_W1l[i] = l;
}

// ---------------- KNN (3-FFMA comparison key) ----------------
__global__ void knn_kernel(const float* __restrict__ xyz1,
                           const float* __restrict__ xyz2,
                           const int* __restrict__ elens,
                           float* __restrict__ out_idx) {
    __shared__ float4 sk[SS];
    int b = blockIdx.y;
    const float* x2 = xyz2 + (size_t)b * SS * 3;
    for (int i = threadIdx.x; i < SS; i += blockDim.x) {
        float x = x2[i * 3 + 0], y = x2[i * 3 + 1], z = x2[i * 3 + 2];
        float ss = __fmaf_rn(z, z, __fmaf_rn(y, y, x * x));
        sk[i] = make_float4(-2.0f * x, -2.0f * y, -2.0f * z, ss);
    }
    __syncthreads();
    int n = blockIdx.x * blockDim.x + threadIdx.x;
    int row = b * NN + n;
    float px = xyz1[(size_t)row * 3 + 0];
    float py = xyz1[(size_t)row * 3 + 1];
    float pz = xyz1[(size_t)row * 3 + 2];
    int sv = elens[b];
    // d' = d2 - |p|^2 : same ordering as d2 for a fixed query
    float b0 = 1e30f, b1 = 1e30f, b2 = 1e30f, b3 = 1e30f, b4 = 1e30f;
    int j0 = 0, j1 = 0, j2 = 0, j3 = 0, j4 = 0;
    for (int s = 0; s < sv; ++s) {
        float4 q = sk[s];
        float d = __fmaf_rn(px, q.x, __fmaf_rn(py, q.y, __fmaf_rn(pz, q.z, q.w)));
        if (d < b4) {
            if (d < b3) {
                b4 = b3; j4 = j3;
                if (d < b2) {
                    b3 = b2; j3 = j2;
                    if (d < b1) {
                        b2 = b1; j2 = j1;
                        if (d < b0) { b1 = b0; j1 = j0; b0 = d; j0 = s; }
                        else        { b1 = d;  j1 = s; }
                    } else { b2 = d; j2 = s; }
                } else { b3 = d; j3 = s; }
            } else { b4 = d; j4 = s; }
        }
    }
    // recompute true squared distances for the 5 winners
    int js[5] = { j0, j1, j2, j3, j4 };
    float rr[5];
#pragma unroll
    for (int t = 0; t < 5; ++t) {
        float4 q = sk[js[t]];
        float sx = -0.5f * q.x, sy = -0.5f * q.y, sz = -0.5f * q.z;
        float dx = px - sx, dy = py - sy, dz = pz - sz;
        float d2 = __fmaf_rn(dz, dz, __fmaf_rn(dy, dy, dx * dx));
        rr[t] = 1.0f / (d2 + EPSF);
    }
    float rsum = ((((rr[0] + rr[1]) + rr[2]) + rr[3]) + rr[4]);
    size_t base = (size_t)row * KNN;
#pragma unroll
    for (int t = 0; t < 5; ++t) {
        g_idx[base + t] = js[t];
        g_w[base + t] = rr[t] / rsum;
        out_idx[base + t] = (float)js[t];
    }
}

// ---------------- interpolation + concat -> g_Ah/g_Al (bf16 split) -------
// One warp per row; float4 gathers from points2 (L2-resident, BW-bound).
__global__ void interp_kernel(const float* __restrict__ points1,
                              const float* __restrict__ points2) {
    int gwarp = (blockIdx.x * blockDim.x + threadIdx.x) >> 5;
    int lane = threadIdx.x & 31;
    if (gwarp >= MM) return;
    int row = gwarp;
    int b = row >> 12;
    const int* ip = g_idx + (size_t)row * KNN;
    const float* wp = g_w + (size_t)row * KNN;
    int i0 = ip[0], i1 = ip[1], i2 = ip[2], i3 = ip[3], i4 = ip[4];
    float w0 = wp[0], w1 = wp[1], w2 = wp[2], w3 = wp[3], w4 = wp[4];
    const float* p2 = points2 + (size_t)b * SS * DD2;
    const float4* r0 = (const float4*)(p2 + (size_t)i0 * DD2);
    const float4* r1 = (const float4*)(p2 + (size_t)i1 * DD2);
    const float4* r2 = (const float4*)(p2 + (size_t)i2 * DD2);
    const float4* r3 = (const float4*)(p2 + (size_t)i3 * DD2);
    const float4* r4 = (const float4*)(p2 + (size_t)i4 * DD2);
    __nv_bfloat16* oh = g_Ah + (size_t)row * KPAD;
    __nv_bfloat16* ol = g_Al + (size_t)row * KPAD;
#pragma unroll
    for (int cc = 0; cc < 3; ++cc) {
        int c4 = cc * 32 + lane;        // float4 index: cols 4*c4 .. 4*c4+3
        float4 v0 = r0[c4], v1 = r1[c4], v2 = r2[c4], v3 = r3[c4], v4 = r4[c4];
        float ax = w0 * v0.x; ax = __fmaf_rn(w1, v1.x, ax); ax = __fmaf_rn(w2, v2.x, ax);
        ax = __fmaf_rn(w3, v3.x, ax); ax = __fmaf_rn(w4, v4.x, ax);
        float ay = w0 * v0.y; ay = __fmaf_rn(w1, v1.y, ay); ay = __fmaf_rn(w2, v2.y, ay);
        ay = __fmaf_rn(w3, v3.y, ay); ay = __fmaf_rn(w4, v4.y, ay);
        float az = w0 * v0.z; az = __fmaf_rn(w1, v1.z, az); az = __fmaf_rn(w2, v2.z, az);
        az = __fmaf_rn(w3, v3.z, az); az = __fmaf_rn(w4, v4.z, az);
        float aw = w0 * v0.w; aw = __fmaf_rn(w1, v1.w, aw); aw = __fmaf_rn(w2, v2.w, aw);
        aw = __fmaf_rn(w3, v3.w, aw); aw = __fmaf_rn(w4, v4.w, aw);
        __nv_bfloat16 hx, lx, hy, ly, hz, lz, hw, lw;
        split_bf16(ax, hx, lx); split_bf16(ay, hy, ly);
        split_bf16(az, hz, lz); split_bf16(aw, hw, lw);
        size_t o = (size_t)row * KPAD + 4 * c4;
        __nv_bfloat162* ph = (__nv_bfloat162*)(oh + 4 * c4 - (size_t)row * KPAD + o) - 0; // flatten
        ((__nv_bfloat162*)(oh + 4 * c4))[0] = __nv_bfloat162{hx, hy};
        ((__nv_bfloat162*)(oh + 4 * c4))[1] = __nv_bfloat162{hz, hw};
        ((__nv_bfloat162*)(ol + 4 * c4))[0] = __nv_bfloat162{lx, ly};
        ((__nv_bfloat162*)(ol + 4 * c4))[1] = __nv_bfloat162{lz, lw};
        (void)ph;
    }
    if (lane < 3) {   // xyz at k = 384..386
        float v = points1[(size_t)row * 3 + lane];
        __nv_bfloat16 h, l; split_bf16(v, h, l);
        oh[384 + lane] = h; ol[384 + lane] = l;
    }
    for (int c = 387 + lane; c < KPAD; c += 32) {
        oh[c] = __float2bfloat16(0.0f); ol[c] = __float2bfloat16(0.0f);
    }
}

// ---------------- bf16x3 GEMM via mma.sync + fused masked stats ----------
// C[M,384] = A[M,nk] * B^T.  CTA tile 128x128, warp 64x32, KC=32, 2 stages.
// (R7 configuration — measured fastest: 164 us, tensor 63%.)
#define STAGE_SZ 32768
#define GEMM_SMEM (2*STAGE_SZ)

__global__ __launch_bounds__(256, 2)
void gemm_mma_kernel(const __nv_bfloat16* __restrict__ Ahp,
                     const __nv_bfloat16* __restrict__ Alp,
                     const __nv_bfloat16* __restrict__ Bhp,
                     const __nv_bfloat16* __restrict__ Blp,
                     float* __restrict__ X, int nk,
                     const int* __restrict__ plens) {
    extern __shared__ __align__(128) char smem[];
    uint32_t sb = smem_u32(smem);
    int tid = threadIdx.x, lane = tid & 31, wid = tid >> 5;
    int wm = wid & 1, wn = wid >> 1;
    int mbase = blockIdx.y * 128, nbase = blockIdx.x * 128;
    int nst = nk >> 5;

    int lrow = tid >> 2, lc = tid & 3;

    auto load_stage = [&](int st) {
        uint32_t sA = sb + (st & 1) * STAGE_SZ;
        int kb = st * 32;
#pragma unroll
        for (int i = 0; i < 2; ++i) {
            int row = lrow + i * 64;
            uint32_t so = row * 64 + ((uint32_t)(lc ^ ((row >> 1) & 3)) << 4);
            size_t ga = (size_t)(mbase + row) * KPAD + kb + lc * 8;
            size_t gb = (size_t)(nbase + row) * KPAD + kb + lc * 8;
            cp16(sA + so,         Ahp + ga);
            cp16(sA + 8192 + so,  Alp + ga);
            cp16(sA + 16384 + so, Bhp + gb);
            cp16(sA + 24576 + so, Blp + gb);
        }
    };

    float acc[4][4][4] = {};

    load_stage(0); CP_COMMIT();

    int arow = lane & 15;            // A: row within m16 tile
    int ahalf = lane >> 4;           // A: k-chunk half
    int brow = (lane & 7) + ((lane >> 4) << 3);  // B: n within 16
    int bhalf = (lane >> 3) & 1;     // B: k-chunk half

    for (int st = 0; st < nst; ++st) {
        if (st + 1 < nst) { load_stage(st + 1); CP_COMMIT(); CP_WAIT1(); }
        else              { CP_WAIT0(); }
        __syncthreads();
        uint32_t sA = sb + (st & 1) * STAGE_SZ;
        uint32_t sAl = sA + 8192, sB = sA + 16384, sBl = sA + 24576;
#pragma unroll
        for (int k2 = 0; k2 < 2; ++k2) {
            int cbase = 2 * k2;
            uint32_t ah[4][4], bh[2][4], bl[2][4];
            uint32_t aso[4], bso[2];
#pragma unroll
            for (int mi = 0; mi < 4; ++mi) {
                int row = wm * 64 + mi * 16 + arow;
                aso[mi] = row * 64 + ((uint32_t)((cbase + ahalf) ^ ((row >> 1) & 3)) << 4);
                LDSM4(ah[mi], sA + aso[mi]);
            }
#pragma unroll
            for (int g = 0; g < 2; ++g) {
                int row = wn * 32 + g * 16 + brow;
                bso[g] = row * 64 + ((uint32_t)((cbase + bhalf) ^ ((row >> 1) & 3)) << 4);
                LDSM4(bh[g], sB + bso[g]);
            }
            // A_hi * B_hi
#pragma unroll
            for (int mi = 0; mi < 4; ++mi)
#pragma unroll
                for (int ni = 0; ni < 4; ++ni)
                    mma16816(acc[mi][ni], ah[mi], &bh[ni >> 1][(ni & 1) * 2]);
            // A_hi * B_lo
#pragma unroll
            for (int g = 0; g < 2; ++g) LDSM4(bl[g], sBl + bso[g]);
#pragma unroll
            for (int mi = 0; mi < 4; ++mi)
#pragma unroll
                for (int ni = 0; ni < 4; ++ni)
                    mma16816(acc[mi][ni], ah[mi], &bl[ni >> 1][(ni & 1) * 2]);
            // A_lo * B_hi  (reuse ah registers for A_lo)
#pragma unroll
            for (int mi = 0; mi < 4; ++mi) LDSM4(ah[mi], sAl + aso[mi]);
#pragma unroll
            for (int mi = 0; mi < 4; ++mi)
#pragma unroll
                for (int ni = 0; ni < 4; ++ni)
                    mma16816(acc[mi][ni], ah[mi], &bh[ni >> 1][(ni & 1) * 2]);
        }
        __syncthreads();
    }

    // ---- output store ----
    int row0 = mbase + wm * 64 + (lane >> 2);
    int col0 = nbase + wn * 32 + 2 * (lane & 3);
#pragma unroll
    for (int mi = 0; mi < 4; ++mi) {
#pragma unroll
        for (int ni = 0; ni < 4; ++ni) {
            int r = row0 + mi * 16;
            int c = col0 + ni * 8;
            float2 v;
            v.x = acc[mi][ni][0]; v.y = acc[mi][ni][1];
            *(float2*)(X + (size_t)r * OC + c) = v;
            v.x = acc[mi][ni][2]; v.y = acc[mi][ni][3];
            *(float2*)(X + (size_t)(r + 8) * OC + c) = v;
        }
    }

    // ---- fused masked stats: per-column sum / sumsq for this 128-row chunk ----
    float* sbuf = (float*)smem;     // 256 floats: [0..127]=sum, [128..255]=sumsq
    __syncthreads();                // mainloop smem reads done, reuse buffer
    sbuf[tid] = 0.0f;
    __syncthreads();

    int bidx = mbase >> 12;
    int lim = plens[bidx] - (mbase & 4095);
    int nv = lim < 0 ? 0 : (lim > 128 ? 128 : lim);
    int ritb = wm * 64 + (lane >> 2);

    float csum[8], csq[8];
#pragma unroll
    for (int t = 0; t < 8; ++t) { csum[t] = 0.0f; csq[t] = 0.0f; }
#pragma unroll
    for (int mi = 0; mi < 4; ++mi) {
#pragma unroll
        for (int j = 0; j < 2; ++j) {
            bool v = (ritb + mi * 16 + 8 * j) < nv;
            if (v) {
#pragma unroll
                for (int ni = 0; ni < 4; ++ni) {
                    float a0 = acc[mi][ni][2 * j + 0];
                    float a1 = acc[mi][ni][2 * j + 1];
                    csum[2 * ni + 0] += a0;
                    csq[2 * ni + 0] = __fmaf_rn(a0, a0, csq[2 * ni + 0]);
                    csum[2 * ni + 1] += a1;
                    csq[2 * ni + 1] = __fmaf_rn(a1, a1, csq[2 * ni + 1]);
                }
            }
        }
    }
#pragma unroll
    for (int m = 4; m <= 16; m <<= 1) {
#pragma unroll
        for (int t = 0; t < 8; ++t) {
            csum[t] += __shfl_xor_sync(0xFFFFFFFFu, csum[t], m);
            csq[t]  += __shfl_xor_sync(0xFFFFFFFFu, csq[t], m);
        }
    }
    if (lane < 4) {
#pragma unroll
        for (int ni = 0; ni < 4; ++ni) {
#pragma unroll
            for (int j = 0; j < 2; ++j) {
                int col = wn * 32 + ni * 8 + 2 * lane + j;
                atomicAdd(&sbuf[col], csum[2 * ni + j]);
                atomicAdd(&sbuf[128 + col], csq[2 * ni + j]);
            }
        }
    }
    __syncthreads();
    int chunk = blockIdx.y;
    if (tid < 128)       g_part[(size_t)chunk * 768 + nbase + tid] = sbuf[tid];
    else                 g_part[(size_t)chunk * 768 + 384 + nbase + (tid - 128)] = sbuf[tid];
}

// ---------------- finalize: mean/var -> scale/shift ----------------------
__global__ void finalize_kernel(const float* __restrict__ gamma,
                                const float* __restrict__ beta,
                                const int* __restrict__ plens, int layer) {
    int c = blockIdx.x;    // 384 blocks
    int t = threadIdx.x;   // 128 threads
    float s = 0.0f, s2 = 0.0f;
    for (int i = t; i < 512; i += 128) {
        s  += g_part[(size_t)i * 768 + c];
        s2 += g_part[(size_t)i * 768 + 384 + c];
    }
    __shared__ float bs[128], bs2[128];
    bs[t] = s; bs2[t] = s2;
    __syncthreads();
    for (int o = 64; o > 0; o >>= 1) {
        if (t < o) { bs[t] += bs[t + o]; bs2[t] += bs2[t + o]; }
        __syncthreads();
    }
    if (t == 0) {
        float nf = 0.0f;
        for (int b = 0; b < BB; ++b) nf += (float)plens[b];
        nf = fmaxf(nf, 1.0f);
        float mean = bs[0] / nf;
        float var = bs2[0] / nf - mean * mean;
        var = fmaxf(var, 0.0f);
        float rs = rsqrtf(var + 1e-5f);
        float sc = gamma[c] * rs;
        g_scale[layer * DD2 + c] = sc;
        g_shift[layer * DD2 + c] = beta[c] - mean * sc;
    }
}

// ---------------- BN+GELU -> bf16 split activations ----------------------
__global__ void bn_gelu_split_kernel(const float* __restrict__ Xp,
                                     const int* __restrict__ plens) {
    size_t i4 = ((size_t)blockIdx.x * blockDim.x + threadIdx.x) * 4;
    if (i4 >= X_ELEMS) return;
    int row = (int)(i4 / DD2);
    int c = (int)(i4 % DD2);
    bool valid = (row & 4095) < plens[row >> 12];
    const float* sc = g_scale + c;
    const float* sh = g_shift + c;
    float4 x = *(const float4*)(Xp + i4);
    float y0 = 0.f, y1 = 0.f, y2 = 0.f, y3 = 0.f;
    if (valid) {
        y0 = gelu_exact(__fmaf_rn(x.x, sc[0], sh[0]));
        y1 = gelu_exact(__fmaf_rn(x.y, sc[1], sh[1]));
        y2 = gelu_exact(__fmaf_rn(x.z, sc[2], sh[2]));
        y3 = gelu_exact(__fmaf_rn(x.w, sc[3], sh[3]));
    }
    __nv_bfloat16 h0, l0, h1, l1, h2, l2, h3, l3;
    split_bf16(y0, h0, l0); split_bf16(y1, h1, l1);
    split_bf16(y2, h2, l2); split_bf16(y3, h3, l3);
    size_t o = (size_t)row * KPAD + c;
    __nv_bfloat162* ph = (__nv_bfloat162*)(g_Ah + o);
    __nv_bfloat162* pl = (__nv_bfloat162*)(g_Al + o);
    ph[0] = __nv_bfloat162{h0, h1}; ph[1] = __nv_bfloat162{h2, h3};
    pl[0] = __nv_bfloat162{l0, l1}; pl[1] = __nv_bfloat162{l2, l3};
}

// ---------------- final masked BN (fp32, in place) -----------------------
__global__ void bn_final_kernel(float* __restrict__ Y,
                                const int* __restrict__ plens) {
    size_t i4 = ((size_t)blockIdx.x * blockDim.x + threadIdx.x) * 4;
    if (i4 >= X_ELEMS) return;
    int row = (int)(i4 / DD2);
    int c = (int)(i4 % DD2);
    bool valid = (row & 4095) < plens[row >> 12];
    const float* sc = g_scale + DD2 + c;
    const float* sh = g_shift + DD2 + c;
    float4 x = *(const float4*)(Y + i4);
    float4 y;
    if (valid) {
        y.x = __fmaf_rn(x.x, sc[0], sh[0]);
        y.y = __fmaf_rn(x.y, sc[1], sh[1]);
        y.z = __fmaf_rn(x.z, sc[2], sh[2]);
        y.w = __fmaf_rn(x.w, sc[3], sh[3]);
    } else {
        y.x = y.y = y.z = y.w = 0.0f;
    }
    *(float4*)(Y + i4) = y;
}

// ---------------- launch ----------------
extern "C" void kernel_launch(void* const* d_in, const int* in_sizes, int n_in,
                              void* d_out, int out_size) {
    const float* xyz1    = (const float*)d_in[0];
    const float* xyz2    = (const float*)d_in[1];
    const float* points1 = (const float*)d_in[2];
    const float* points2 = (const float*)d_in[3];
    const int*   plens   = (const int*)d_in[4];
    const int*   elens   = (const int*)d_in[5];
    const float* W0 = (const float*)d_in[7];
    const float* g0 = (const float*)d_in[8];
    const float* b0 = (const float*)d_in[9];
    const float* W1 = (const float*)d_in[10];
    const float* g1 = (const float*)d_in[11];
    const float* b1 = (const float*)d_in[12];
    float* out = (float*)d_out;

    __nv_bfloat16 *pAh, *pAl, *pW0h, *pW0l, *pW1h, *pW1l;
    float* pX0;
    cudaGetSymbolAddress((void**)&pAh, g_Ah);
    cudaGetSymbolAddress((void**)&pAl, g_Al);
    cudaGetSymbolAddress((void**)&pX0, g_X0);
    cudaGetSymbolAddress((void**)&pW0h, g_W0h);
    cudaGetSymbolAddress((void**)&pW0l, g_W0l);
    cudaGetSymbolAddress((void**)&pW1h, g_W1h);
    cudaGetSymbolAddress((void**)&pW1l, g_W1l);

    cudaFuncSetAttribute(gemm_mma_kernel,
                         cudaFuncAttributeMaxDynamicSharedMemorySize, GEMM_SMEM);

    prep_weights_kernel<<<(OC * KPAD + 255) / 256, 256>>>(W0, W1);
    knn_kernel<<<dim3(NN / 256, BB), 256>>>(xyz1, xyz2, elens, out + X_ELEMS);
    interp_kernel<<<MM / 8, 256>>>(points1, points2);

    // layer 0: X0 = new_points @ W0^T  (K = 416 padded), stats fused
    gemm_mma_kernel<<<dim3(3, MM / 128), 256, GEMM_SMEM>>>(pAh, pAl, pW0h, pW0l, pX0, 416, plens);
    finalize_kernel<<<384, 128>>>(g0, b0, plens, 0);
    bn_gelu_split_kernel<<<(unsigned)(X_ELEMS / 4 + 255) / 256, 256>>>(pX0, plens);

    // layer 1: out = act @ W1^T  (K = 384), stats fused
    gemm_mma_kernel<<<dim3(3, MM / 128), 256, GEMM_SMEM>>>(pAh, pAl, pW1h, pW1l, out, 384, plens);
    finalize_kernel<<<384, 128>>>(g1, b1, plens, 1);
    bn_final_kernel<<<(unsigned)(X_ELEMS / 4 + 255) / 256, 256>>>(out, plens);
}

// round 12
// speedup vs baseline: 1.6182x; 1.2203x over previous
#include <cuda_runtime.h>
#include <cuda_bf16.h>
#include <math.h>
#include <stdint.h>

// ---------------- problem constants ----------------
#define BB   16
#define NN   4096
#define SS   512
#define DD2  384
#define KNN  5
#define MM   (BB*NN)          // 65536 rows
#define KPAD 416              // padded K stride (bf16 arrays), 13*32, covers 387
#define OC   384              // output channels
#define X_ELEMS ((size_t)MM*DD2)   // 25165824
#define EPSF 1.1920929e-7f

// K-order permutation: k 0..383 = interpolated feature k, k 384..386 = xyz, 387.. = 0.
// Weights permuted identically, so the GEMM result is unchanged.
// Masked-row skipping: rows >= point_lens[b] never influence any observed output
// (stats are masked, bn_final writes constant 0), so whole 128-row GEMM chunks
// beyond the valid range are skipped and their scratch left as garbage.

// ---------------- device scratch (static, no allocation) ----------------
__device__ __align__(128) __nv_bfloat16 g_Ah[(size_t)MM * KPAD];
__device__ __align__(128) __nv_bfloat16 g_Al[(size_t)MM * KPAD];
__device__ __align__(128) float g_X0[(size_t)MM * DD2];
__device__ __align__(128) __nv_bfloat16 g_W0h[OC * KPAD];
__device__ __align__(128) __nv_bfloat16 g_W0l[OC * KPAD];
__device__ __align__(128) __nv_bfloat16 g_W1h[OC * KPAD];
__device__ __align__(128) __nv_bfloat16 g_W1l[OC * KPAD];
__device__ int   g_idx[MM * KNN];
__device__ float g_w[MM * KNN];
__device__ float g_part[512 * 2 * DD2];
__device__ float g_scale[2 * DD2];
__device__ float g_shift[2 * DD2];

// ---------------- helpers ----------------
__device__ __forceinline__ uint32_t smem_u32(const void* p) {
    uint32_t a;
    asm("{ .reg .u64 t; cvta.to.shared.u64 t, %1; cvt.u32.u64 %0, t; }" : "=r"(a) : "l"(p));
    return a;
}
__device__ __forceinline__ void cp16(uint32_t s, const void* g) {
    asm volatile("cp.async.cg.shared.global [%0], [%1], 16;" :: "r"(s), "l"(g));
}
#define CP_COMMIT() asm volatile("cp.async.commit_group;")
#define CP_WAIT1()  asm volatile("cp.async.wait_group 1;")
#define CP_WAIT0()  asm volatile("cp.async.wait_group 0;")

#define LDSM4(r, addr) \
    asm volatile("ldmatrix.sync.aligned.m8n8.x4.shared.b16 {%0,%1,%2,%3}, [%4];" \
        : "=r"((r)[0]), "=r"((r)[1]), "=r"((r)[2]), "=r"((r)[3]) : "r"(addr))

__device__ __forceinline__ void mma16816(float* c, const uint32_t* a, const uint32_t* b) {
    asm volatile(
        "mma.sync.aligned.m16n8k16.row.col.f32.bf16.bf16.f32 "
        "{%0,%1,%2,%3}, {%4,%5,%6,%7}, {%8,%9}, {%0,%1,%2,%3};"
        : "+f"(c[0]), "+f"(c[1]), "+f"(c[2]), "+f"(c[3])
        : "r"(a[0]), "r"(a[1]), "r"(a[2]), "r"(a[3]), "r"(b[0]), "r"(b[1]));
}

__device__ __forceinline__ float gelu_exact(float v) {
    return 0.5f * v * (1.0f + erff(v * 0.7071067811865476f));
}
__device__ __forceinline__ void split_bf16(float v, __nv_bfloat16 &h, __nv_bfloat16 &l) {
    h = __float2bfloat16(v);
    l = __float2bfloat16(v - __bfloat162float(h));
}

// ---------------- weight prep: permute + split + pad ----------------
__global__ void prep_weights_kernel(const float* __restrict__ W0,
                                    const float* __restrict__ W1) {
    int i = blockIdx.x * blockDim.x + threadIdx.x;
    if (i >= OC * KPAD) return;
    int o = i / KPAD, k = i % KPAD;
    float v0 = 0.0f, v1 = 0.0f;
    if (k < 384)      v0 = W0[o * 387 + 3 + k];     // feature part
    else if (k < 387) v0 = W0[o * 387 + (k - 384)]; // xyz part
    if (k < 384)      v1 = W1[o * 384 + k];
    __nv_bfloat16 h, l;
    split_bf16(v0, h, l); g_W0h[i] = h; g_W0l[i] = l;
    split_bf16(v1, h, l); g_W1h[i] = h; g_W1l[i] = l;
}

// ---------------- KNN (3-FFMA comparison key) ----------------
__global__ void knn_kernel(const float* __restrict__ xyz1,
                           const float* __restrict__ xyz2,
                           const int* __restrict__ elens,
                           float* __restrict__ out_idx) {
    __shared__ float4 sk[SS];
    int b = blockIdx.y;
    const float* x2 = xyz2 + (size_t)b * SS * 3;
    for (int i = threadIdx.x; i < SS; i += blockDim.x) {
        float x = x2[i * 3 + 0], y = x2[i * 3 + 1], z = x2[i * 3 + 2];
        float ss = __fmaf_rn(z, z, __fmaf_rn(y, y, x * x));
        sk[i] = make_float4(-2.0f * x, -2.0f * y, -2.0f * z, ss);
    }
    __syncthreads();
    int n = blockIdx.x * blockDim.x + threadIdx.x;
    int row = b * NN + n;
    float px = xyz1[(size_t)row * 3 + 0];
    float py = xyz1[(size_t)row * 3 + 1];
    float pz = xyz1[(size_t)row * 3 + 2];
    int sv = elens[b];
    // d' = d2 - |p|^2 : same ordering as d2 for a fixed query
    float b0 = 1e30f, b1 = 1e30f, b2 = 1e30f, b3 = 1e30f, b4 = 1e30f;
    int j0 = 0, j1 = 0, j2 = 0, j3 = 0, j4 = 0;
    for (int s = 0; s < sv; ++s) {
        float4 q = sk[s];
        float d = __fmaf_rn(px, q.x, __fmaf_rn(py, q.y, __fmaf_rn(pz, q.z, q.w)));
        if (d < b4) {
            if (d < b3) {
                b4 = b3; j4 = j3;
                if (d < b2) {
                    b3 = b2; j3 = j2;
                    if (d < b1) {
                        b2 = b1; j2 = j1;
                        if (d < b0) { b1 = b0; j1 = j0; b0 = d; j0 = s; }
                        else        { b1 = d;  j1 = s; }
                    } else { b2 = d; j2 = s; }
                } else { b3 = d; j3 = s; }
            } else { b4 = d; j4 = s; }
        }
    }
    // recompute true squared distances for the 5 winners
    int js[5] = { j0, j1, j2, j3, j4 };
    float rr[5];
#pragma unroll
    for (int t = 0; t < 5; ++t) {
        float4 q = sk[js[t]];
        float sx = -0.5f * q.x, sy = -0.5f * q.y, sz = -0.5f * q.z;
        float dx = px - sx, dy = py - sy, dz = pz - sz;
        float d2 = __fmaf_rn(dz, dz, __fmaf_rn(dy, dy, dx * dx));
        rr[t] = 1.0f / (d2 + EPSF);
    }
    float rsum = ((((rr[0] + rr[1]) + rr[2]) + rr[3]) + rr[4]);
    size_t base = (size_t)row * KNN;
#pragma unroll
    for (int t = 0; t < 5; ++t) {
        g_idx[base + t] = js[t];
        g_w[base + t] = rr[t] / rsum;
        out_idx[base + t] = (float)js[t];
    }
}

// ---------------- interpolation + concat -> g_Ah/g_Al (bf16 split) -------
// One warp per row; float4 gathers from points2 (L2-resident, BW-bound).
// Invalid rows (>= plens[b]) are skipped entirely.
__global__ void interp_kernel(const float* __restrict__ points1,
                              const float* __restrict__ points2,
                              const int* __restrict__ plens) {
    int gwarp = (blockIdx.x * blockDim.x + threadIdx.x) >> 5;
    int lane = threadIdx.x & 31;
    if (gwarp >= MM) return;
    int row = gwarp;
    int b = row >> 12;
    if ((row & 4095) >= plens[b]) return;   // masked row: output never observed
    const int* ip = g_idx + (size_t)row * KNN;
    const float* wp = g_w + (size_t)row * KNN;
    int i0 = ip[0], i1 = ip[1], i2 = ip[2], i3 = ip[3], i4 = ip[4];
    float w0 = wp[0], w1 = wp[1], w2 = wp[2], w3 = wp[3], w4 = wp[4];
    const float* p2 = points2 + (size_t)b * SS * DD2;
    const float4* r0 = (const float4*)(p2 + (size_t)i0 * DD2);
    const float4* r1 = (const float4*)(p2 + (size_t)i1 * DD2);
    const float4* r2 = (const float4*)(p2 + (size_t)i2 * DD2);
    const float4* r3 = (const float4*)(p2 + (size_t)i3 * DD2);
    const float4* r4 = (const float4*)(p2 + (size_t)i4 * DD2);
    __nv_bfloat16* oh = g_Ah + (size_t)row * KPAD;
    __nv_bfloat16* ol = g_Al + (size_t)row * KPAD;
#pragma unroll
    for (int cc = 0; cc < 3; ++cc) {
        int c4 = cc * 32 + lane;        // float4 index: cols 4*c4 .. 4*c4+3
        float4 v0 = r0[c4], v1 = r1[c4], v2 = r2[c4], v3 = r3[c4], v4 = r4[c4];
        float ax = w0 * v0.x; ax = __fmaf_rn(w1, v1.x, ax); ax = __fmaf_rn(w2, v2.x, ax);
        ax = __fmaf_rn(w3, v3.x, ax); ax = __fmaf_rn(w4, v4.x, ax);
        float ay = w0 * v0.y; ay = __fmaf_rn(w1, v1.y, ay); ay = __fmaf_rn(w2, v2.y, ay);
        ay = __fmaf_rn(w3, v3.y, ay); ay = __fmaf_rn(w4, v4.y, ay);
        float az = w0 * v0.z; az = __fmaf_rn(w1, v1.z, az); az = __fmaf_rn(w2, v2.z, az);
        az = __fmaf_rn(w3, v3.z, az); az = __fmaf_rn(w4, v4.z, az);
        float aw = w0 * v0.w; aw = __fmaf_rn(w1, v1.w, aw); aw = __fmaf_rn(w2, v2.w, aw);
        aw = __fmaf_rn(w3, v3.w, aw); aw = __fmaf_rn(w4, v4.w, aw);
        __nv_bfloat16 hx, lx, hy, ly, hz, lz, hw, lw;
        split_bf16(ax, hx, lx); split_bf16(ay, hy, ly);
        split_bf16(az, hz, lz); split_bf16(aw, hw, lw);
        ((__nv_bfloat162*)(oh + 4 * c4))[0] = __nv_bfloat162{hx, hy};
        ((__nv_bfloat162*)(oh + 4 * c4))[1] = __nv_bfloat162{hz, hw};
        ((__nv_bfloat162*)(ol + 4 * c4))[0] = __nv_bfloat162{lx, ly};
        ((__nv_bfloat162*)(ol + 4 * c4))[1] = __nv_bfloat162{lz, lw};
    }
    if (lane < 3) {   // xyz at k = 384..386
        float v = points1[(size_t)row * 3 + lane];
        __nv_bfloat16 h, l; split_bf16(v, h, l);
        oh[384 + lane] = h; ol[384 + lane] = l;
    }
    for (int c = 387 + lane; c < KPAD; c += 32) {
        oh[c] = __float2bfloat16(0.0f); ol[c] = __float2bfloat16(0.0f);
    }
}

// ---------------- bf16x3 GEMM via mma.sync + fused masked stats ----------
// C[M,384] = A[M,nk] * B^T.  CTA tile 128x128, warp 64x32, KC=32, 2 stages.
// (R7 configuration — measured fastest: 164 us, tensor 63%.)
// CTAs whose 128-row chunk is fully masked write zero stats and exit.
#define STAGE_SZ 32768
#define GEMM_SMEM (2*STAGE_SZ)

__global__ __launch_bounds__(256, 2)
void gemm_mma_kernel(const __nv_bfloat16* __restrict__ Ahp,
                     const __nv_bfloat16* __restrict__ Alp,
                     const __nv_bfloat16* __restrict__ Bhp,
                     const __nv_bfloat16* __restrict__ Blp,
                     float* __restrict__ X, int nk,
                     const int* __restrict__ plens) {
    extern __shared__ __align__(128) char smem[];
    uint32_t sb = smem_u32(smem);
    int tid = threadIdx.x, lane = tid & 31, wid = tid >> 5;
    int wm = wid & 1, wn = wid >> 1;
    int mbase = blockIdx.y * 128, nbase = blockIdx.x * 128;
    int nst = nk >> 5;
    int chunk = blockIdx.y;

    // masked-chunk early exit: rows entirely >= plens[b]
    int bidx = mbase >> 12;
    int lim = plens[bidx] - (mbase & 4095);
    if (lim <= 0) {
        if (tid < 128)       g_part[(size_t)chunk * 768 + nbase + tid] = 0.0f;
        else                 g_part[(size_t)chunk * 768 + 384 + nbase + (tid - 128)] = 0.0f;
        return;
    }
    int nv = lim > 128 ? 128 : lim;

    int lrow = tid >> 2, lc = tid & 3;

    auto load_stage = [&](int st) {
        uint32_t sA = sb + (st & 1) * STAGE_SZ;
        int kb = st * 32;
#pragma unroll
        for (int i = 0; i < 2; ++i) {
            int row = lrow + i * 64;
            uint32_t so = row * 64 + ((uint32_t)(lc ^ ((row >> 1) & 3)) << 4);
            size_t ga = (size_t)(mbase + row) * KPAD + kb + lc * 8;
            size_t gb = (size_t)(nbase + row) * KPAD + kb + lc * 8;
            cp16(sA + so,         Ahp + ga);
            cp16(sA + 8192 + so,  Alp + ga);
            cp16(sA + 16384 + so, Bhp + gb);
            cp16(sA + 24576 + so, Blp + gb);
        }
    };

    float acc[4][4][4] = {};

    load_stage(0); CP_COMMIT();

    int arow = lane & 15;            // A: row within m16 tile
    int ahalf = lane >> 4;           // A: k-chunk half
    int brow = (lane & 7) + ((lane >> 4) << 3);  // B: n within 16
    int bhalf = (lane >> 3) & 1;     // B: k-chunk half

    for (int st = 0; st < nst; ++st) {
        if (st + 1 < nst) { load_stage(st + 1); CP_COMMIT(); CP_WAIT1(); }
        else              { CP_WAIT0(); }
        __syncthreads();
        uint32_t sA = sb + (st & 1) * STAGE_SZ;
        uint32_t sAl = sA + 8192, sB = sA + 16384, sBl = sA + 24576;
#pragma unroll
        for (int k2 = 0; k2 < 2; ++k2) {
            int cbase = 2 * k2;
            uint32_t ah[4][4], bh[2][4], bl[2][4];
            uint32_t aso[4], bso[2];
#pragma unroll
            for (int mi = 0; mi < 4; ++mi) {
                int row = wm * 64 + mi * 16 + arow;
                aso[mi] = row * 64 + ((uint32_t)((cbase + ahalf) ^ ((row >> 1) & 3)) << 4);
                LDSM4(ah[mi], sA + aso[mi]);
            }
#pragma unroll
            for (int g = 0; g < 2; ++g) {
                int row = wn * 32 + g * 16 + brow;
                bso[g] = row * 64 + ((uint32_t)((cbase + bhalf) ^ ((row >> 1) & 3)) << 4);
                LDSM4(bh[g], sB + bso[g]);
            }
            // A_hi * B_hi
#pragma unroll
            for (int mi = 0; mi < 4; ++mi)
#pragma unroll
                for (int ni = 0; ni < 4; ++ni)
                    mma16816(acc[mi][ni], ah[mi], &bh[ni >> 1][(ni & 1) * 2]);
            // A_hi * B_lo
#pragma unroll
            for (int g = 0; g < 2; ++g) LDSM4(bl[g], sBl + bso[g]);
#pragma unroll
            for (int mi = 0; mi < 4; ++mi)
#pragma unroll
                for (int ni = 0; ni < 4; ++ni)
                    mma16816(acc[mi][ni], ah[mi], &bl[ni >> 1][(ni & 1) * 2]);
            // A_lo * B_hi  (reuse ah registers for A_lo)
#pragma unroll
            for (int mi = 0; mi < 4; ++mi) LDSM4(ah[mi], sAl + aso[mi]);
#pragma unroll
            for (int mi = 0; mi < 4; ++mi)
#pragma unroll
                for (int ni = 0; ni < 4; ++ni)
                    mma16816(acc[mi][ni], ah[mi], &bh[ni >> 1][(ni & 1) * 2]);
        }
        __syncthreads();
    }

    // ---- output store ----
    int row0 = mbase + wm * 64 + (lane >> 2);
    int col0 = nbase + wn * 32 + 2 * (lane & 3);
#pragma unroll
    for (int mi = 0; mi < 4; ++mi) {
#pragma unroll
        for (int ni = 0; ni < 4; ++ni) {
            int r = row0 + mi * 16;
            int c = col0 + ni * 8;
            float2 v;
            v.x = acc[mi][ni][0]; v.y = acc[mi][ni][1];
            *(float2*)(X + (size_t)r * OC + c) = v;
            v.x = acc[mi][ni][2]; v.y = acc[mi][ni][3];
            *(float2*)(X + (size_t)(r + 8) * OC + c) = v;
        }
    }

    // ---- fused masked stats: per-column sum / sumsq for this 128-row chunk ----
    float* sbuf = (float*)smem;     // 256 floats: [0..127]=sum, [128..255]=sumsq
    __syncthreads();                // mainloop smem reads done, reuse buffer
    sbuf[tid] = 0.0f;
    __syncthreads();

    int ritb = wm * 64 + (lane >> 2);

    float csum[8], csq[8];
#pragma unroll
    for (int t = 0; t < 8; ++t) { csum[t] = 0.0f; csq[t] = 0.0f; }
#pragma unroll
    for (int mi = 0; mi < 4; ++mi) {
#pragma unroll
        for (int j = 0; j < 2; ++j) {
            bool v = (ritb + mi * 16 + 8 * j) < nv;
            if (v) {
#pragma unroll
                for (int ni = 0; ni < 4; ++ni) {
                    float a0 = acc[mi][ni][2 * j + 0];
                    float a1 = acc[mi][ni][2 * j + 1];
                    csum[2 * ni + 0] += a0;
                    csq[2 * ni + 0] = __fmaf_rn(a0, a0, csq[2 * ni + 0]);
                    csum[2 * ni + 1] += a1;
                    csq[2 * ni + 1] = __fmaf_rn(a1, a1, csq[2 * ni + 1]);
                }
            }
        }
    }
#pragma unroll
    for (int m = 4; m <= 16; m <<= 1) {
#pragma unroll
        for (int t = 0; t < 8; ++t) {
            csum[t] += __shfl_xor_sync(0xFFFFFFFFu, csum[t], m);
            csq[t]  += __shfl_xor_sync(0xFFFFFFFFu, csq[t], m);
        }
    }
    if (lane < 4) {
#pragma unroll
        for (int ni = 0; ni < 4; ++ni) {
#pragma unroll
            for (int j = 0; j < 2; ++j) {
                int col = wn * 32 + ni * 8 + 2 * lane + j;
                atomicAdd(&sbuf[col], csum[2 * ni + j]);
                atomicAdd(&sbuf[128 + col], csq[2 * ni + j]);
            }
        }
    }
    __syncthreads();
    if (tid < 128)       g_part[(size_t)chunk * 768 + nbase + tid] = sbuf[tid];
    else                 g_part[(size_t)chunk * 768 + 384 + nbase + (tid - 128)] = sbuf[tid];
}

// ---------------- finalize: mean/var -> scale/shift ----------------------
__global__ void finalize_kernel(const float* __restrict__ gamma,
                                const float* __restrict__ beta,
                                const int* __restrict__ plens, int layer) {
    int c = blockIdx.x;    // 384 blocks
    int t = threadIdx.x;   // 128 threads
    float s = 0.0f, s2 = 0.0f;
    for (int i = t; i < 512; i += 128) {
        s  += g_part[(size_t)i * 768 + c];
        s2 += g_part[(size_t)i * 768 + 384 + c];
    }
    __shared__ float bs[128], bs2[128];
    bs[t] = s; bs2[t] = s2;
    __syncthreads();
    for (int o = 64; o > 0; o >>= 1) {
        if (t < o) { bs[t] += bs[t + o]; bs2[t] += bs2[t + o]; }
        __syncthreads();
    }
    if (t == 0) {
        float nf = 0.0f;
        for (int b = 0; b < BB; ++b) nf += (float)plens[b];
        nf = fmaxf(nf, 1.0f);
        float mean = bs[0] / nf;
        float var = bs2[0] / nf - mean * mean;
        var = fmaxf(var, 0.0f);
        float rs = rsqrtf(var + 1e-5f);
        float sc = gamma[c] * rs;
        g_scale[layer * DD2 + c] = sc;
        g_shift[layer * DD2 + c] = beta[c] - mean * sc;
    }
}

// ---------------- BN+GELU -> bf16 split activations ----------------------
// Invalid rows: skipped entirely (their activations are never observed).
__global__ void bn_gelu_split_kernel(const float* __restrict__ Xp,
                                     const int* __restrict__ plens) {
    size_t i4 = ((size_t)blockIdx.x * blockDim.x + threadIdx.x) * 4;
    if (i4 >= X_ELEMS) return;
    int row = (int)(i4 / DD2);
    int c = (int)(i4 % DD2);
    if ((row & 4095) >= plens[row >> 12]) return;
    const float* sc = g_scale + c;
    const float* sh = g_shift + c;
    float4 x = *(const float4*)(Xp + i4);
    float y0 = gelu_exact(__fmaf_rn(x.x, sc[0], sh[0]));
    float y1 = gelu_exact(__fmaf_rn(x.y, sc[1], sh[1]));
    float y2 = gelu_exact(__fmaf_rn(x.z, sc[2], sh[2]));
    float y3 = gelu_exact(__fmaf_rn(x.w, sc[3], sh[3]));
    __nv_bfloat16 h0, l0, h1, l1, h2, l2, h3, l3;
    split_bf16(y0, h0, l0); split_bf16(y1, h1, l1);
    split_bf16(y2, h2, l2); split_bf16(y3, h3, l3);
    size_t o = (size_t)row * KPAD + c;
    __nv_bfloat162* ph = (__nv_bfloat162*)(g_Ah + o);
    __nv_bfloat162* pl = (__nv_bfloat162*)(g_Al + o);
    ph[0] = __nv_bfloat162{h0, h1}; ph[1] = __nv_bfloat162{h2, h3};
    pl[0] = __nv_bfloat162{l0, l1}; pl[1] = __nv_bfloat162{l2, l3};
}

// ---------------- final masked BN (fp32, in place) -----------------------
__global__ void bn_final_kernel(float* __restrict__ Y,
                                const int* __restrict__ plens) {
    size_t i4 = ((size_t)blockIdx.x * blockDim.x + threadIdx.x) * 4;
    if (i4 >= X_ELEMS) return;
    int row = (int)(i4 / DD2);
    int c = (int)(i4 % DD2);
    bool valid = (row & 4095) < plens[row >> 12];
    float4 y;
    if (valid) {
        const float* sc = g_scale + DD2 + c;
        const float* sh = g_shift + DD2 + c;
        float4 x = *(const float4*)(Y + i4);
        y.x = __fmaf_rn(x.x, sc[0], sh[0]);
        y.y = __fmaf_rn(x.y, sc[1], sh[1]);
        y.z = __fmaf_rn(x.z, sc[2], sh[2]);
        y.w = __fmaf_rn(x.w, sc[3], sh[3]);
    } else {
        y.x = y.y = y.z = y.w = 0.0f;
    }
    *(float4*)(Y + i4) = y;
}

// ---------------- launch ----------------
extern "C" void kernel_launch(void* const* d_in, const int* in_sizes, int n_in,
                              void* d_out, int out_size) {
    const float* xyz1    = (const float*)d_in[0];
    const float* xyz2    = (const float*)d_in[1];
    const float* points1 = (const float*)d_in[2];
    const float* points2 = (const float*)d_in[3];
    const int*   plens   = (const int*)d_in[4];
    const int*   elens   = (const int*)d_in[5];
    const float* W0 = (const float*)d_in[7];
    const float* g0 = (const float*)d_in[8];
    const float* b0 = (const float*)d_in[9];
    const float* W1 = (const float*)d_in[10];
    const float* g1 = (const float*)d_in[11];
    const float* b1 = (const float*)d_in[12];
    float* out = (float*)d_out;

    __nv_bfloat16 *pAh, *pAl, *pW0h, *pW0l, *pW1h, *pW1l;
    float* pX0;
    cudaGetSymbolAddress((void**)&pAh, g_Ah);
    cudaGetSymbolAddress((void**)&pAl, g_Al);
    cudaGetSymbolAddress((void**)&pX0, g_X0);
    cudaGetSymbolAddress((void**)&pW0h, g_W0h);
    cudaGetSymbolAddress((void**)&pW0l, g_W0l);
    cudaGetSymbolAddress((void**)&pW1h, g_W1h);
    cudaGetSymbolAddress((void**)&pW1l, g_W1l);

    cudaFuncSetAttribute(gemm_mma_kernel,
                         cudaFuncAttributeMaxDynamicSharedMemorySize, GEMM_SMEM);

    prep_weights_kernel<<<(OC * KPAD + 255) / 256, 256>>>(W0, W1);
    knn_kernel<<<dim3(NN / 256, BB), 256>>>(xyz1, xyz2, elens, out + X_ELEMS);
    interp_kernel<<<MM / 8, 256>>>(points1, points2, plens);

    // layer 0: X0 = new_points @ W0^T  (K = 416 padded), stats fused
    gemm_mma_kernel<<<dim3(3, MM / 128), 256, GEMM_SMEM>>>(pAh, pAl, pW0h, pW0l, pX0, 416, plens);
    finalize_kernel<<<384, 128>>>(g0, b0, plens, 0);
    bn_gelu_split_kernel<<<(unsigned)(X_ELEMS / 4 + 255) / 256, 256>>>(pX0, plens);

    // layer 1: out = act @ W1^T  (K = 384), stats fused
    gemm_mma_kernel<<<dim3(3, MM / 128), 256, GEMM_SMEM>>>(pAh, pAl, pW1h, pW1l, out, 384, plens);
    finalize_kernel<<<384, 128>>>(g1, b1, plens, 1);
    bn_final_kernel<<<(unsigned)(X_ELEMS / 4 + 255) / 256, 256>>>(out, plens);
}

// round 14
// speedup vs baseline: 1.8946x; 1.1708x over previous
#include <cuda_runtime.h>
#include <cuda_bf16.h>
#include <math.h>
#include <stdint.h>

// ---------------- problem constants ----------------
#define BB   16
#define NN   4096
#define SS   512
#define DD2  384
#define KNN  5
#define MM   (BB*NN)          // 65536 rows
#define SROWS (BB*SS)         // 8192 rows of points2
#define KPAD 416              // stride for activation bf16 arrays (gemm1 A)
#define OC   384              // output channels
#define X_ELEMS ((size_t)MM*DD2)   // 25165824
#define EPSF 1.1920929e-7f

// Layer-0 restructuring (linearity): X0 = sum_k w_k * Y2[idx_k] + xyz @ W0xyz^T
// where Y2 = points2 @ W0feat^T is computed over only 8192 rows.

// ---------------- device scratch (static, no allocation) ----------------
__device__ __align__(128) __nv_bfloat16 g_Ah[(size_t)MM * KPAD];   // gemm1 A hi
__device__ __align__(128) __nv_bfloat16 g_Al[(size_t)MM * KPAD];   // gemm1 A lo
__device__ __align__(128) float g_X0[(size_t)MM * DD2];
__device__ __align__(128) float g_Y2[(size_t)SROWS * DD2];
__device__ __align__(128) __nv_bfloat16 g_P2h[(size_t)SROWS * DD2];
__device__ __align__(128) __nv_bfloat16 g_P2l[(size_t)SROWS * DD2];
__device__ __align__(128) __nv_bfloat16 g_Wf0h[OC * DD2];
__device__ __align__(128) __nv_bfloat16 g_Wf0l[OC * DD2];
__device__ __align__(128) __nv_bfloat16 g_W1h[OC * DD2];
__device__ __align__(128) __nv_bfloat16 g_W1l[OC * DD2];
__device__ __align__(128) float g_Wxyz[3 * DD2];   // [j][o] transposed
__device__ int   g_idx[MM * KNN];
__device__ float g_w[MM * KNN];
__device__ float g_part[512 * 2 * DD2];
__device__ float g_scale[2 * DD2];
__device__ float g_shift[2 * DD2];

// ---------------- helpers ----------------
__device__ __forceinline__ uint32_t smem_u32(const void* p) {
    uint32_t a;
    asm("{ .reg .u64 t; cvta.to.shared.u64 t, %1; cvt.u32.u64 %0, t; }" : "=r"(a) : "l"(p));
    return a;
}
__device__ __forceinline__ void cp16(uint32_t s, const void* g) {
    asm volatile("cp.async.cg.shared.global [%0], [%1], 16;" :: "r"(s), "l"(g));
}
#define CP_COMMIT() asm volatile("cp.async.commit_group;")
#define CP_WAIT1()  asm volatile("cp.async.wait_group 1;")
#define CP_WAIT0()  asm volatile("cp.async.wait_group 0;")

#define LDSM4(r, addr) \
    asm volatile("ldmatrix.sync.aligned.m8n8.x4.shared.b16 {%0,%1,%2,%3}, [%4];" \
        : "=r"((r)[0]), "=r"((r)[1]), "=r"((r)[2]), "=r"((r)[3]) : "r"(addr))

__device__ __forceinline__ void mma16816(float* c, const uint32_t* a, const uint32_t* b) {
    asm volatile(
        "mma.sync.aligned.m16n8k16.row.col.f32.bf16.bf16.f32 "
        "{%0,%1,%2,%3}, {%4,%5,%6,%7}, {%8,%9}, {%0,%1,%2,%3};"
        : "+f"(c[0]), "+f"(c[1]), "+f"(c[2]), "+f"(c[3])
        : "r"(a[0]), "r"(a[1]), "r"(a[2]), "r"(a[3]), "r"(b[0]), "r"(b[1]));
}

__device__ __forceinline__ float gelu_exact(float v) {
    return 0.5f * v * (1.0f + erff(v * 0.7071067811865476f));
}
__device__ __forceinline__ void split_bf16(float v, __nv_bfloat16 &h, __nv_bfloat16 &l) {
    h = __float2bfloat16(v);
    l = __float2bfloat16(v - __bfloat162float(h));
}

// ---------------- weight prep ----------------
__global__ void prep_weights_kernel(const float* __restrict__ W0,
                                    const float* __restrict__ W1) {
    int i = blockIdx.x * blockDim.x + threadIdx.x;
    if (i >= OC * DD2) return;
    int o = i / DD2, k = i % DD2;
    __nv_bfloat16 h, l;
    split_bf16(W0[o * 387 + 3 + k], h, l); g_Wf0h[i] = h; g_Wf0l[i] = l;
    split_bf16(W1[o * DD2 + k], h, l);     g_W1h[i] = h; g_W1l[i] = l;
    if (i < 3 * DD2) {
        int j = i / DD2, o2 = i % DD2;
        g_Wxyz[i] = W0[o2 * 387 + j];
    }
}

// ---------------- points2 bf16 split ----------------
__global__ void prep_p2_kernel(const float* __restrict__ points2) {
    size_t i4 = ((size_t)blockIdx.x * blockDim.x + threadIdx.x) * 4;
    if (i4 >= (size_t)SROWS * DD2) return;
    float4 v = *(const float4*)(points2 + i4);
    __nv_bfloat16 h0, l0, h1, l1, h2, l2, h3, l3;
    split_bf16(v.x, h0, l0); split_bf16(v.y, h1, l1);
    split_bf16(v.z, h2, l2); split_bf16(v.w, h3, l3);
    __nv_bfloat162* ph = (__nv_bfloat162*)(g_P2h + i4);
    __nv_bfloat162* pl = (__nv_bfloat162*)(g_P2l + i4);
    ph[0] = __nv_bfloat162{h0, h1}; ph[1] = __nv_bfloat162{h2, h3};
    pl[0] = __nv_bfloat162{l0, l1}; pl[1] = __nv_bfloat162{l2, l3};
}

// ---------------- KNN (3-FFMA comparison key) ----------------
__global__ void knn_kernel(const float* __restrict__ xyz1,
                           const float* __restrict__ xyz2,
                           const int* __restrict__ elens,
                           float* __restrict__ out_idx) {
    __shared__ float4 sk[SS];
    int b = blockIdx.y;
    const float* x2 = xyz2 + (size_t)b * SS * 3;
    for (int i = threadIdx.x; i < SS; i += blockDim.x) {
        float x = x2[i * 3 + 0], y = x2[i * 3 + 1], z = x2[i * 3 + 2];
        float ss = __fmaf_rn(z, z, __fmaf_rn(y, y, x * x));
        sk[i] = make_float4(-2.0f * x, -2.0f * y, -2.0f * z, ss);
    }
    __syncthreads();
    int n = blockIdx.x * blockDim.x + threadIdx.x;
    int row = b * NN + n;
    float px = xyz1[(size_t)row * 3 + 0];
    float py = xyz1[(size_t)row * 3 + 1];
    float pz = xyz1[(size_t)row * 3 + 2];
    int sv = elens[b];
    float b0 = 1e30f, b1 = 1e30f, b2 = 1e30f, b3 = 1e30f, b4 = 1e30f;
    int j0 = 0, j1 = 0, j2 = 0, j3 = 0, j4 = 0;
    for (int s = 0; s < sv; ++s) {
        float4 q = sk[s];
        float d = __fmaf_rn(px, q.x, __fmaf_rn(py, q.y, __fmaf_rn(pz, q.z, q.w)));
        if (d < b4) {
            if (d < b3) {
                b4 = b3; j4 = j3;
                if (d < b2) {
                    b3 = b2; j3 = j2;
                    if (d < b1) {
                        b2 = b1; j2 = j1;
                        if (d < b0) { b1 = b0; j1 = j0; b0 = d; j0 = s; }
                        else        { b1 = d;  j1 = s; }
                    } else { b2 = d; j2 = s; }
                } else { b3 = d; j3 = s; }
            } else { b4 = d; j4 = s; }
        }
    }
    int js[5] = { j0, j1, j2, j3, j4 };
    float rr[5];
#pragma unroll
    for (int t = 0; t < 5; ++t) {
        float4 q = sk[js[t]];
        float sx = -0.5f * q.x, sy = -0.5f * q.y, sz = -0.5f * q.z;
        float dx = px - sx, dy = py - sy, dz = pz - sz;
        float d2 = __fmaf_rn(dz, dz, __fmaf_rn(dy, dy, dx * dx));
        rr[t] = 1.0f / (d2 + EPSF);
    }
    float rsum = ((((rr[0] + rr[1]) + rr[2]) + rr[3]) + rr[4]);
    size_t base = (size_t)row * KNN;
#pragma unroll
    for (int t = 0; t < 5; ++t) {
        g_idx[base + t] = js[t];
        g_w[base + t] = rr[t] / rsum;
        out_idx[base + t] = (float)js[t];
    }
}

// ---------------- combine: X0 = interp(Y2) + xyz@Wxyz, fused stats -------
// grid 512 (one block per 128-row chunk), block 256 (8 warps, 16 rows each).
__global__ __launch_bounds__(256)
void combine_kernel(const float* __restrict__ points1,
                    const int* __restrict__ plens) {
    __shared__ float sW[3 * DD2];    // Wxyz transposed
    __shared__ float sbuf[2 * DD2];  // per-chunk stats
    int tid = threadIdx.x, lane = tid & 31, wid = tid >> 5;
    int chunk = blockIdx.x;
    for (int i = tid; i < 3 * DD2; i += 256) sW[i] = g_Wxyz[i];
    for (int i = tid; i < 2 * DD2; i += 256) sbuf[i] = 0.0f;
    __syncthreads();

    int r0 = chunk * 128;
    int b = r0 >> 12;
    int lim = plens[b] - (r0 & 4095);
    int nv = lim < 0 ? 0 : (lim > 128 ? 128 : lim);
    const float* Y2b = g_Y2 + (size_t)b * SS * DD2;

#pragma unroll 1
    for (int p = 0; p < 3; ++p) {
        int colb = p * 128 + lane * 4;
        float4 wx = *(const float4*)&sW[0 * DD2 + colb];
        float4 wy = *(const float4*)&sW[1 * DD2 + colb];
        float4 wz = *(const float4*)&sW[2 * DD2 + colb];
        float s0 = 0.f, s1 = 0.f, s2c = 0.f, s3 = 0.f;
        float q0 = 0.f, q1 = 0.f, q2 = 0.f, q3 = 0.f;
#pragma unroll 1
        for (int i = 0; i < 16; ++i) {
            int r = wid + 8 * i;
            if (r >= nv) continue;
            int row = r0 + r;
            const int* ip = &g_idx[(size_t)row * KNN];
            const float* wp = &g_w[(size_t)row * KNN];
            int i0 = ip[0], i1 = ip[1], i2 = ip[2], i3 = ip[3], i4 = ip[4];
            float w0 = wp[0], w1 = wp[1], w2 = wp[2], w3 = wp[3], w4 = wp[4];
            float px = points1[(size_t)row * 3 + 0];
            float py = points1[(size_t)row * 3 + 1];
            float pz = points1[(size_t)row * 3 + 2];
            float4 y0 = *(const float4*)(Y2b + (size_t)i0 * DD2 + colb);
            float4 y1 = *(const float4*)(Y2b + (size_t)i1 * DD2 + colb);
            float4 y2 = *(const float4*)(Y2b + (size_t)i2 * DD2 + colb);
            float4 y3 = *(const float4*)(Y2b + (size_t)i3 * DD2 + colb);
            float4 y4 = *(const float4*)(Y2b + (size_t)i4 * DD2 + colb);
            float4 a;
            a.x = __fmaf_rn(pz, wz.x, __fmaf_rn(py, wy.x, px * wx.x));
            a.y = __fmaf_rn(pz, wz.y, __fmaf_rn(py, wy.y, px * wx.y));
            a.z = __fmaf_rn(pz, wz.z, __fmaf_rn(py, wy.z, px * wx.z));
            a.w = __fmaf_rn(pz, wz.w, __fmaf_rn(py, wy.w, px * wx.w));
            a.x = __fmaf_rn(w0, y0.x, a.x); a.y = __fmaf_rn(w0, y0.y, a.y);
            a.z = __fmaf_rn(w0, y0.z, a.z); a.w = __fmaf_rn(w0, y0.w, a.w);
            a.x = __fmaf_rn(w1, y1.x, a.x); a.y = __fmaf_rn(w1, y1.y, a.y);
            a.z = __fmaf_rn(w1, y1.z, a.z); a.w = __fmaf_rn(w1, y1.w, a.w);
            a.x = __fmaf_rn(w2, y2.x, a.x); a.y = __fmaf_rn(w2, y2.y, a.y);
            a.z = __fmaf_rn(w2, y2.z, a.z); a.w = __fmaf_rn(w2, y2.w, a.w);
            a.x = __fmaf_rn(w3, y3.x, a.x); a.y = __fmaf_rn(w3, y3.y, a.y);
            a.z = __fmaf_rn(w3, y3.z, a.z); a.w = __fmaf_rn(w3, y3.w, a.w);
            a.x = __fmaf_rn(w4, y4.x, a.x); a.y = __fmaf_rn(w4, y4.y, a.y);
            a.z = __fmaf_rn(w4, y4.z, a.z); a.w = __fmaf_rn(w4, y4.w, a.w);
            *(float4*)(g_X0 + (size_t)row * DD2 + colb) = a;
            s0 += a.x; q0 = __fmaf_rn(a.x, a.x, q0);
            s1 += a.y; q1 = __fmaf_rn(a.y, a.y, q1);
            s2c += a.z; q2 = __fmaf_rn(a.z, a.z, q2);
            s3 += a.w; q3 = __fmaf_rn(a.w, a.w, q3);
        }
        atomicAdd(&sbuf[colb + 0], s0); atomicAdd(&sbuf[DD2 + colb + 0], q0);
        atomicAdd(&sbuf[colb + 1], s1); atomicAdd(&sbuf[DD2 + colb + 1], q1);
        atomicAdd(&sbuf[colb + 2], s2c); atomicAdd(&sbuf[DD2 + colb + 2], q2);
        atomicAdd(&sbuf[colb + 3], s3); atomicAdd(&sbuf[DD2 + colb + 3], q3);
    }
    __syncthreads();
    for (int i = tid; i < DD2; i += 256) {
        g_part[(size_t)chunk * 768 + i] = sbuf[i];
        g_part[(size_t)chunk * 768 + DD2 + i] = sbuf[DD2 + i];
    }
}

// ---------------- bf16x3 GEMM via mma.sync (+optional fused stats) -------
// C[M,384] = A[M,K] * B^T.  CTA tile 128x128, warp 64x32, KC=32, 2 stages.
#define STAGE_SZ 32768
#define GEMM_SMEM (2*STAGE_SZ)

__global__ __launch_bounds__(256, 2)
void gemm_mma_kernel(const __nv_bfloat16* __restrict__ Ahp,
                     const __nv_bfloat16* __restrict__ Alp,
                     const __nv_bfloat16* __restrict__ Bhp,
                     const __nv_bfloat16* __restrict__ Blp,
                     float* __restrict__ X, int nst, int lda, int ldb,
                     const int* __restrict__ plens) {
    extern __shared__ __align__(128) char smem[];
    uint32_t sb = smem_u32(smem);
    int tid = threadIdx.x, lane = tid & 31, wid = tid >> 5;
    int wm = wid & 1, wn = wid >> 1;
    int mbase = blockIdx.y * 128, nbase = blockIdx.x * 128;
    int chunk = blockIdx.y;

    int nv = 128;
    if (plens) {
        int bidx = mbase >> 12;
        int lim = plens[bidx] - (mbase & 4095);
        if (lim <= 0) {
            if (tid < 128)       g_part[(size_t)chunk * 768 + nbase + tid] = 0.0f;
            else                 g_part[(size_t)chunk * 768 + 384 + nbase + (tid - 128)] = 0.0f;
            return;
        }
        nv = lim > 128 ? 128 : lim;
    }

    int lrow = tid >> 2, lc = tid & 3;

    auto load_stage = [&](int st) {
        uint32_t sA = sb + (st & 1) * STAGE_SZ;
        int kb = st * 32;
#pragma unroll
        for (int i = 0; i < 2; ++i) {
            int row = lrow + i * 64;
            uint32_t so = row * 64 + ((uint32_t)(lc ^ ((row >> 1) & 3)) << 4);
            size_t ga = (size_t)(mbase + row) * lda + kb + lc * 8;
            size_t gb = (size_t)(nbase + row) * ldb + kb + lc * 8;
            cp16(sA + so,         Ahp + ga);
            cp16(sA + 8192 + so,  Alp + ga);
            cp16(sA + 16384 + so, Bhp + gb);
            cp16(sA + 24576 + so, Blp + gb);
        }
    };

    float acc[4][4][4] = {};

    load_stage(0); CP_COMMIT();

    int arow = lane & 15;
    int ahalf = lane >> 4;
    int brow = (lane & 7) + ((lane >> 4) << 3);
    int bhalf = (lane >> 3) & 1;

    for (int st = 0; st < nst; ++st) {
        if (st + 1 < nst) { load_stage(st + 1); CP_COMMIT(); CP_WAIT1(); }
        else              { CP_WAIT0(); }
        __syncthreads();
        uint32_t sA = sb + (st & 1) * STAGE_SZ;
        uint32_t sAl = sA + 8192, sB = sA + 16384, sBl = sA + 24576;
#pragma unroll
        for (int k2 = 0; k2 < 2; ++k2) {
            int cbase = 2 * k2;
            uint32_t ah[4][4], bh[2][4], bl[2][4];
            uint32_t aso[4], bso[2];
#pragma unroll
            for (int mi = 0; mi < 4; ++mi) {
                int row = wm * 64 + mi * 16 + arow;
                aso[mi] = row * 64 + ((uint32_t)((cbase + ahalf) ^ ((row >> 1) & 3)) << 4);
                LDSM4(ah[mi], sA + aso[mi]);
            }
#pragma unroll
            for (int g = 0; g < 2; ++g) {
                int row = wn * 32 + g * 16 + brow;
                bso[g] = row * 64 + ((uint32_t)((cbase + bhalf) ^ ((row >> 1) & 3)) << 4);
                LDSM4(bh[g], sB + bso[g]);
            }
#pragma unroll
            for (int mi = 0; mi < 4; ++mi)
#pragma unroll
                for (int ni = 0; ni < 4; ++ni)
                    mma16816(acc[mi][ni], ah[mi], &bh[ni >> 1][(ni & 1) * 2]);
#pragma unroll
            for (int g = 0; g < 2; ++g) LDSM4(bl[g], sBl + bso[g]);
#pragma unroll
            for (int mi = 0; mi < 4; ++mi)
#pragma unroll
                for (int ni = 0; ni < 4; ++ni)
                    mma16816(acc[mi][ni], ah[mi], &bl[ni >> 1][(ni & 1) * 2]);
#pragma unroll
            for (int mi = 0; mi < 4; ++mi) LDSM4(ah[mi], sAl + aso[mi]);
#pragma unroll
            for (int mi = 0; mi < 4; ++mi)
#pragma unroll
                for (int ni = 0; ni < 4; ++ni)
                    mma16816(acc[mi][ni], ah[mi], &bh[ni >> 1][(ni & 1) * 2]);
        }
        __syncthreads();
    }

    // ---- output store ----
    int row0 = mbase + wm * 64 + (lane >> 2);
    int col0 = nbase + wn * 32 + 2 * (lane & 3);
#pragma unroll
    for (int mi = 0; mi < 4; ++mi) {
#pragma unroll
        for (int ni = 0; ni < 4; ++ni) {
            int r = row0 + mi * 16;
            int c = col0 + ni * 8;
            float2 v;
            v.x = acc[mi][ni][0]; v.y = acc[mi][ni][1];
            *(float2*)(X + (size_t)r * OC + c) = v;
            v.x = acc[mi][ni][2]; v.y = acc[mi][ni][3];
            *(float2*)(X + (size_t)(r + 8) * OC + c) = v;
        }
    }

    if (!plens) return;

    // ---- fused masked stats ----
    float* sbuf = (float*)smem;
    __syncthreads();
    sbuf[tid] = 0.0f;
    __syncthreads();

    int ritb = wm * 64 + (lane >> 2);
    float csum[8], csq[8];
#pragma unroll
    for (int t = 0; t < 8; ++t) { csum[t] = 0.0f; csq[t] = 0.0f; }
#pragma unroll
    for (int mi = 0; mi < 4; ++mi) {
#pragma unroll
        for (int j = 0; j < 2; ++j) {
            bool v = (ritb + mi * 16 + 8 * j) < nv;
            if (v) {
#pragma unroll
                for (int ni = 0; ni < 4; ++ni) {
                    float a0 = acc[mi][ni][2 * j + 0];
                    float a1 = acc[mi][ni][2 * j + 1];
                    csum[2 * ni + 0] += a0;
                    csq[2 * ni + 0] = __fmaf_rn(a0, a0, csq[2 * ni + 0]);
                    csum[2 * ni + 1] += a1;
                    csq[2 * ni + 1] = __fmaf_rn(a1, a1, csq[2 * ni + 1]);
                }
            }
        }
    }
#pragma unroll
    for (int m = 4; m <= 16; m <<= 1) {
#pragma unroll
        for (int t = 0; t < 8; ++t) {
            csum[t] += __shfl_xor_sync(0xFFFFFFFFu, csum[t], m);
            csq[t]  += __shfl_xor_sync(0xFFFFFFFFu, csq[t], m);
        }
    }
    if (lane < 4) {
#pragma unroll
        for (int ni = 0; ni < 4; ++ni) {
#pragma unroll
            for (int j = 0; j < 2; ++j) {
                int col = wn * 32 + ni * 8 + 2 * lane + j;
                atomicAdd(&sbuf[col], csum[2 * ni + j]);
                atomicAdd(&sbuf[128 + col], csq[2 * ni + j]);
            }
        }
    }
    __syncthreads();
    if (tid < 128)       g_part[(size_t)chunk * 768 + nbase + tid] = sbuf[tid];
    else                 g_part[(size_t)chunk * 768 + 384 + nbase + (tid - 128)] = sbuf[tid];
}

// ---------------- finalize: mean/var -> scale/shift ----------------------
__global__ void finalize_kernel(const float* __restrict__ gamma,
                                const float* __restrict__ beta,
                                const int* __restrict__ plens, int layer) {
    int c = blockIdx.x;
    int t = threadIdx.x;
    float s = 0.0f, s2 = 0.0f;
    for (int i = t; i < 512; i += 128) {
        s  += g_part[(size_t)i * 768 + c];
        s2 += g_part[(size_t)i * 768 + 384 + c];
    }
    __shared__ float bs[128], bs2[128];
    bs[t] = s; bs2[t] = s2;
    __syncthreads();
    for (int o = 64; o > 0; o >>= 1) {
        if (t < o) { bs[t] += bs[t + o]; bs2[t] += bs2[t + o]; }
        __syncthreads();
    }
    if (t == 0) {
        float nf = 0.0f;
        for (int b = 0; b < BB; ++b) nf += (float)plens[b];
        nf = fmaxf(nf, 1.0f);
        float mean = bs[0] / nf;
        float var = bs2[0] / nf - mean * mean;
        var = fmaxf(var, 0.0f);
        float rs = rsqrtf(var + 1e-5f);
        float sc = gamma[c] * rs;
        g_scale[layer * DD2 + c] = sc;
        g_shift[layer * DD2 + c] = beta[c] - mean * sc;
    }
}

// ---------------- BN+GELU -> bf16 split activations ----------------------
__global__ void bn_gelu_split_kernel(const float* __restrict__ Xp,
                                     const int* __restrict__ plens) {
    size_t i4 = ((size_t)blockIdx.x * blockDim.x + threadIdx.x) * 4;
    if (i4 >= X_ELEMS) return;
    int row = (int)(i4 / DD2);
    int c = (int)(i4 % DD2);
    if ((row & 4095) >= plens[row >> 12]) return;
    const float* sc = g_scale + c;
    const float* sh = g_shift + c;
    float4 x = *(const float4*)(Xp + i4);
    float y0 = gelu_exact(__fmaf_rn(x.x, sc[0], sh[0]));
    float y1 = gelu_exact(__fmaf_rn(x.y, sc[1], sh[1]));
    float y2 = gelu_exact(__fmaf_rn(x.z, sc[2], sh[2]));
    float y3 = gelu_exact(__fmaf_rn(x.w, sc[3], sh[3]));
    __nv_bfloat16 h0, l0, h1, l1, h2, l2, h3, l3;
    split_bf16(y0, h0, l0); split_bf16(y1, h1, l1);
    split_bf16(y2, h2, l2); split_bf16(y3, h3, l3);
    size_t o = (size_t)row * KPAD + c;
    __nv_bfloat162* ph = (__nv_bfloat162*)(g_Ah + o);
    __nv_bfloat162* pl = (__nv_bfloat162*)(g_Al + o);
    ph[0] = __nv_bfloat162{h0, h1}; ph[1] = __nv_bfloat162{h2, h3};
    pl[0] = __nv_bfloat162{l0, l1}; pl[1] = __nv_bfloat162{l2, l3};
}

// ---------------- final masked BN (fp32, in place) -----------------------
__global__ void bn_final_kernel(float* __restrict__ Y,
                                const int* __restrict__ plens) {
    size_t i4 = ((size_t)blockIdx.x * blockDim.x + threadIdx.x) * 4;
    if (i4 >= X_ELEMS) return;
    int row = (int)(i4 / DD2);
    int c = (int)(i4 % DD2);
    bool valid = (row & 4095) < plens[row >> 12];
    float4 y;
    if (valid) {
        const float* sc = g_scale + DD2 + c;
        const float* sh = g_shift + DD2 + c;
        float4 x = *(const float4*)(Y + i4);
        y.x = __fmaf_rn(x.x, sc[0], sh[0]);
        y.y = __fmaf_rn(x.y, sc[1], sh[1]);
        y.z = __fmaf_rn(x.z, sc[2], sh[2]);
        y.w = __fmaf_rn(x.w, sc[3], sh[3]);
    } else {
        y.x = y.y = y.z = y.w = 0.0f;
    }
    *(float4*)(Y + i4) = y;
}

// ---------------- launch ----------------
extern "C" void kernel_launch(void* const* d_in, const int* in_sizes, int n_in,
                              void* d_out, int out_size) {
    const float* xyz1    = (const float*)d_in[0];
    const float* xyz2    = (const float*)d_in[1];
    const float* points1 = (const float*)d_in[2];
    const float* points2 = (const float*)d_in[3];
    const int*   plens   = (const int*)d_in[4];
    const int*   elens   = (const int*)d_in[5];
    const float* W0 = (const float*)d_in[7];
    const float* g0 = (const float*)d_in[8];
    const float* b0 = (const float*)d_in[9];
    const float* W1 = (const float*)d_in[10];
    const float* g1 = (const float*)d_in[11];
    const float* b1 = (const float*)d_in[12];
    float* out = (float*)d_out;

    __nv_bfloat16 *pAh, *pAl, *pP2h, *pP2l, *pWf0h, *pWf0l, *pW1h, *pW1l;
    float *pX0, *pY2;
    cudaGetSymbolAddress((void**)&pAh, g_Ah);
    cudaGetSymbolAddress((void**)&pAl, g_Al);
    cudaGetSymbolAddress((void**)&pX0, g_X0);
    cudaGetSymbolAddress((void**)&pY2, g_Y2);
    cudaGetSymbolAddress((void**)&pP2h, g_P2h);
    cudaGetSymbolAddress((void**)&pP2l, g_P2l);
    cudaGetSymbolAddress((void**)&pWf0h, g_Wf0h);
    cudaGetSymbolAddress((void**)&pWf0l, g_Wf0l);
    cudaGetSymbolAddress((void**)&pW1h, g_W1h);
    cudaGetSymbolAddress((void**)&pW1l, g_W1l);

    cudaFuncSetAttribute(gemm_mma_kernel,
                         cudaFuncAttributeMaxDynamicSharedMemorySize, GEMM_SMEM);

    prep_weights_kernel<<<(OC * DD2 + 255) / 256, 256>>>(W0, W1);
    prep_p2_kernel<<<(unsigned)((size_t)SROWS * DD2 / 4 + 255) / 256, 256>>>(points2);
    knn_kernel<<<dim3(NN / 256, BB), 256>>>(xyz1, xyz2, elens, out + X_ELEMS);

    // small GEMM: Y2 = points2 @ W0feat^T  (8192 x 384 x 384)
    gemm_mma_kernel<<<dim3(3, SROWS / 128), 256, GEMM_SMEM>>>(
        pP2h, pP2l, pWf0h, pWf0l, pY2, 12, DD2, DD2, nullptr);

    // combine: X0 = interp(Y2) + xyz term, fused layer-0 stats
    combine_kernel<<<512, 256>>>(points1, plens);
    finalize_kernel<<<384, 128>>>(g0, b0, plens, 0);
    bn_gelu_split_kernel<<<(unsigned)(X_ELEMS / 4 + 255) / 256, 256>>>(pX0, plens);

    // layer 1: out = act @ W1^T  (K = 384), stats fused, masked-chunk skip
    gemm_mma_kernel<<<dim3(3, MM / 128), 256, GEMM_SMEM>>>(
        pAh, pAl, pW1h, pW1l, out, 12, KPAD, DD2, plens);
    finalize_kernel<<<384, 128>>>(g1, b1, plens, 1);
    bn_final_kernel<<<(unsigned)(X_ELEMS / 4 + 255) / 256, 256>>>(out, plens);
}

// round 15
// speedup vs baseline: 1.9949x; 1.0529x over previous
#include <cuda_runtime.h>
#include <cuda_bf16.h>
#include <math.h>
#include <stdint.h>

// ---------------- problem constants ----------------
#define BB   16
#define NN   4096
#define SS   512
#define DD2  384
#define KNN  5
#define MM   (BB*NN)          // 65536 rows
#define SROWS (BB*SS)         // 8192 rows of points2
#define KPAD 416              // stride for activation bf16 arrays (gemm1 A)
#define OC   384              // output channels
#define X_ELEMS ((size_t)MM*DD2)   // 25165824
#define EPSF 1.1920929e-7f

// Layer-0 restructuring (linearity): X0 = sum_k w_k * Y2[idx_k] + xyz @ W0xyz^T
// where Y2 = points2 @ W0feat^T is computed over only 8192 rows.
// R15: knn and the small GEMM are independent -> fused into one block-specialized
// launch (blocks 0..191 = GEMM, 192..447 = knn) to overlap scalar and tensor work.

// ---------------- device scratch (static, no allocation) ----------------
__device__ __align__(128) __nv_bfloat16 g_Ah[(size_t)MM * KPAD];   // gemm1 A hi
__device__ __align__(128) __nv_bfloat16 g_Al[(size_t)MM * KPAD];   // gemm1 A lo
__device__ __align__(128) float g_X0[(size_t)MM * DD2];
__device__ __align__(128) float g_Y2[(size_t)SROWS * DD2];
__device__ __align__(128) __nv_bfloat16 g_P2h[(size_t)SROWS * DD2];
__device__ __align__(128) __nv_bfloat16 g_P2l[(size_t)SROWS * DD2];
__device__ __align__(128) __nv_bfloat16 g_Wf0h[OC * DD2];
__device__ __align__(128) __nv_bfloat16 g_Wf0l[OC * DD2];
__device__ __align__(128) __nv_bfloat16 g_W1h[OC * DD2];
__device__ __align__(128) __nv_bfloat16 g_W1l[OC * DD2];
__device__ __align__(128) float g_Wxyz[3 * DD2];   // [j][o] transposed
__device__ int   g_idx[MM * KNN];
__device__ float g_w[MM * KNN];
__device__ float g_part[512 * 2 * DD2];
__device__ float g_scale[2 * DD2];
__device__ float g_shift[2 * DD2];

// ---------------- helpers ----------------
__device__ __forceinline__ uint32_t smem_u32(const void* p) {
    uint32_t a;
    asm("{ .reg .u64 t; cvta.to.shared.u64 t, %1; cvt.u32.u64 %0, t; }" : "=r"(a) : "l"(p));
    return a;
}
__device__ __forceinline__ void cp16(uint32_t s, const void* g) {
    asm volatile("cp.async.cg.shared.global [%0], [%1], 16;" :: "r"(s), "l"(g));
}
#define CP_COMMIT() asm volatile("cp.async.commit_group;")
#define CP_WAIT1()  asm volatile("cp.async.wait_group 1;")
#define CP_WAIT0()  asm volatile("cp.async.wait_group 0;")

#define LDSM4(r, addr) \
    asm volatile("ldmatrix.sync.aligned.m8n8.x4.shared.b16 {%0,%1,%2,%3}, [%4];" \
        : "=r"((r)[0]), "=r"((r)[1]), "=r"((r)[2]), "=r"((r)[3]) : "r"(addr))

__device__ __forceinline__ void mma16816(float* c, const uint32_t* a, const uint32_t* b) {
    asm volatile(
        "mma.sync.aligned.m16n8k16.row.col.f32.bf16.bf16.f32 "
        "{%0,%1,%2,%3}, {%4,%5,%6,%7}, {%8,%9}, {%0,%1,%2,%3};"
        : "+f"(c[0]), "+f"(c[1]), "+f"(c[2]), "+f"(c[3])
        : "r"(a[0]), "r"(a[1]), "r"(a[2]), "r"(a[3]), "r"(b[0]), "r"(b[1]));
}

__device__ __forceinline__ float gelu_exact(float v) {
    return 0.5f * v * (1.0f + erff(v * 0.7071067811865476f));
}
__device__ __forceinline__ void split_bf16(float v, __nv_bfloat16 &h, __nv_bfloat16 &l) {
    h = __float2bfloat16(v);
    l = __float2bfloat16(v - __bfloat162float(h));
}

// ---------------- weight prep ----------------
__global__ void prep_weights_kernel(const float* __restrict__ W0,
                                    const float* __restrict__ W1) {
    int i = blockIdx.x * blockDim.x + threadIdx.x;
    if (i >= OC * DD2) return;
    int o = i / DD2, k = i % DD2;
    __nv_bfloat16 h, l;
    split_bf16(W0[o * 387 + 3 + k], h, l); g_Wf0h[i] = h; g_Wf0l[i] = l;
    split_bf16(W1[o * DD2 + k], h, l);     g_W1h[i] = h; g_W1l[i] = l;
    if (i < 3 * DD2) {
        int j = i / DD2, o2 = i % DD2;
        g_Wxyz[i] = W0[o2 * 387 + j];
    }
}

// ---------------- points2 bf16 split ----------------
__global__ void prep_p2_kernel(const float* __restrict__ points2) {
    size_t i4 = ((size_t)blockIdx.x * blockDim.x + threadIdx.x) * 4;
    if (i4 >= (size_t)SROWS * DD2) return;
    float4 v = *(const float4*)(points2 + i4);
    __nv_bfloat16 h0, l0, h1, l1, h2, l2, h3, l3;
    split_bf16(v.x, h0, l0); split_bf16(v.y, h1, l1);
    split_bf16(v.z, h2, l2); split_bf16(v.w, h3, l3);
    __nv_bfloat162* ph = (__nv_bfloat162*)(g_P2h + i4);
    __nv_bfloat162* pl = (__nv_bfloat162*)(g_P2l + i4);
    ph[0] = __nv_bfloat162{h0, h1}; ph[1] = __nv_bfloat162{h2, h3};
    pl[0] = __nv_bfloat162{l0, l1}; pl[1] = __nv_bfloat162{l2, l3};
}

// ---------------- GEMM body (shared by small gemm and layer-1 gemm) ------
// C[128 rows, 128 cols tile] = A[.,K] * B^T.  warp 64x32, KC=32, 2 stages.
#define STAGE_SZ 32768
#define GEMM_SMEM (2*STAGE_SZ)

template <bool STATS>
__device__ __forceinline__ void gemm_body(
    char* smem, int bxn, int by,
    const __nv_bfloat16* __restrict__ Ahp, const __nv_bfloat16* __restrict__ Alp,
    const __nv_bfloat16* __restrict__ Bhp, const __nv_bfloat16* __restrict__ Blp,
    float* __restrict__ X, int nst, int lda, int ldb,
    const int* __restrict__ plens) {
    uint32_t sb = smem_u32(smem);
    int tid = threadIdx.x, lane = tid & 31, wid = tid >> 5;
    int wm = wid & 1, wn = wid >> 1;
    int mbase = by * 128, nbase = bxn * 128;
    int chunk = by;

    int nv = 128;
    if (STATS) {
        int bidx = mbase >> 12;
        int lim = plens[bidx] - (mbase & 4095);
        if (lim <= 0) {
            if (tid < 128)       g_part[(size_t)chunk * 768 + nbase + tid] = 0.0f;
            else                 g_part[(size_t)chunk * 768 + 384 + nbase + (tid - 128)] = 0.0f;
            return;
        }
        nv = lim > 128 ? 128 : lim;
    }

    int lrow = tid >> 2, lc = tid & 3;

    auto load_stage = [&](int st) {
        uint32_t sA = sb + (st & 1) * STAGE_SZ;
        int kb = st * 32;
#pragma unroll
        for (int i = 0; i < 2; ++i) {
            int row = lrow + i * 64;
            uint32_t so = row * 64 + ((uint32_t)(lc ^ ((row >> 1) & 3)) << 4);
            size_t ga = (size_t)(mbase + row) * lda + kb + lc * 8;
            size_t gb = (size_t)(nbase + row) * ldb + kb + lc * 8;
            cp16(sA + so,         Ahp + ga);
            cp16(sA + 8192 + so,  Alp + ga);
            cp16(sA + 16384 + so, Bhp + gb);
            cp16(sA + 24576 + so, Blp + gb);
        }
    };

    float acc[4][4][4] = {};

    load_stage(0); CP_COMMIT();

    int arow = lane & 15;
    int ahalf = lane >> 4;
    int brow = (lane & 7) + ((lane >> 4) << 3);
    int bhalf = (lane >> 3) & 1;

    for (int st = 0; st < nst; ++st) {
        if (st + 1 < nst) { load_stage(st + 1); CP_COMMIT(); CP_WAIT1(); }
        else              { CP_WAIT0(); }
        __syncthreads();
        uint32_t sA = sb + (st & 1) * STAGE_SZ;
        uint32_t sAl = sA + 8192, sB = sA + 16384, sBl = sA + 24576;
#pragma unroll
        for (int k2 = 0; k2 < 2; ++k2) {
            int cbase = 2 * k2;
            uint32_t ah[4][4], bh[2][4], bl[2][4];
            uint32_t aso[4], bso[2];
#pragma unroll
            for (int mi = 0; mi < 4; ++mi) {
                int row = wm * 64 + mi * 16 + arow;
                aso[mi] = row * 64 + ((uint32_t)((cbase + ahalf) ^ ((row >> 1) & 3)) << 4);
                LDSM4(ah[mi], sA + aso[mi]);
            }
#pragma unroll
            for (int g = 0; g < 2; ++g) {
                int row = wn * 32 + g * 16 + brow;
                bso[g] = row * 64 + ((uint32_t)((cbase + bhalf) ^ ((row >> 1) & 3)) << 4);
                LDSM4(bh[g], sB + bso[g]);
            }
#pragma unroll
            for (int mi = 0; mi < 4; ++mi)
#pragma unroll
                for (int ni = 0; ni < 4; ++ni)
                    mma16816(acc[mi][ni], ah[mi], &bh[ni >> 1][(ni & 1) * 2]);
#pragma unroll
            for (int g = 0; g < 2; ++g) LDSM4(bl[g], sBl + bso[g]);
#pragma unroll
            for (int mi = 0; mi < 4; ++mi)
#pragma unroll
                for (int ni = 0; ni < 4; ++ni)
                    mma16816(acc[mi][ni], ah[mi], &bl[ni >> 1][(ni & 1) * 2]);
#pragma unroll
            for (int mi = 0; mi < 4; ++mi) LDSM4(ah[mi], sAl + aso[mi]);
#pragma unroll
            for (int mi = 0; mi < 4; ++mi)
#pragma unroll
                for (int ni = 0; ni < 4; ++ni)
                    mma16816(acc[mi][ni], ah[mi], &bh[ni >> 1][(ni & 1) * 2]);
        }
        __syncthreads();
    }

    // ---- output store ----
    int row0 = mbase + wm * 64 + (lane >> 2);
    int col0 = nbase + wn * 32 + 2 * (lane & 3);
#pragma unroll
    for (int mi = 0; mi < 4; ++mi) {
#pragma unroll
        for (int ni = 0; ni < 4; ++ni) {
            int r = row0 + mi * 16;
            int c = col0 + ni * 8;
            float2 v;
            v.x = acc[mi][ni][0]; v.y = acc[mi][ni][1];
            *(float2*)(X + (size_t)r * OC + c) = v;
            v.x = acc[mi][ni][2]; v.y = acc[mi][ni][3];
            *(float2*)(X + (size_t)(r + 8) * OC + c) = v;
        }
    }

    if (!STATS) return;

    // ---- fused masked stats ----
    float* sbuf = (float*)smem;
    __syncthreads();
    sbuf[tid] = 0.0f;
    __syncthreads();

    int ritb = wm * 64 + (lane >> 2);
    float csum[8], csq[8];
#pragma unroll
    for (int t = 0; t < 8; ++t) { csum[t] = 0.0f; csq[t] = 0.0f; }
#pragma unroll
    for (int mi = 0; mi < 4; ++mi) {
#pragma unroll
        for (int j = 0; j < 2; ++j) {
            bool v = (ritb + mi * 16 + 8 * j) < nv;
            if (v) {
#pragma unroll
                for (int ni = 0; ni < 4; ++ni) {
                    float a0 = acc[mi][ni][2 * j + 0];
                    float a1 = acc[mi][ni][2 * j + 1];
                    csum[2 * ni + 0] += a0;
                    csq[2 * ni + 0] = __fmaf_rn(a0, a0, csq[2 * ni + 0]);
                    csum[2 * ni + 1] += a1;
                    csq[2 * ni + 1] = __fmaf_rn(a1, a1, csq[2 * ni + 1]);
                }
            }
        }
    }
#pragma unroll
    for (int m = 4; m <= 16; m <<= 1) {
#pragma unroll
        for (int t = 0; t < 8; ++t) {
            csum[t] += __shfl_xor_sync(0xFFFFFFFFu, csum[t], m);
            csq[t]  += __shfl_xor_sync(0xFFFFFFFFu, csq[t], m);
        }
    }
    if (lane < 4) {
#pragma unroll
        for (int ni = 0; ni < 4; ++ni) {
#pragma unroll
            for (int j = 0; j < 2; ++j) {
                int col = wn * 32 + ni * 8 + 2 * lane + j;
                atomicAdd(&sbuf[col], csum[2 * ni + j]);
                atomicAdd(&sbuf[128 + col], csq[2 * ni + j]);
            }
        }
    }
    __syncthreads();
    if (tid < 128)       g_part[(size_t)chunk * 768 + nbase + tid] = sbuf[tid];
    else                 g_part[(size_t)chunk * 768 + 384 + nbase + (tid - 128)] = sbuf[tid];
}

// ---------------- KNN body (3-FFMA comparison key) ----------------
__device__ __forceinline__ void knn_body(
    int kb, const float* __restrict__ xyz1, const float* __restrict__ xyz2,
    const int* __restrict__ elens, float* __restrict__ out_idx) {
    __shared__ float4 sk[SS];
    int b = kb >> 4;
    int n = (kb & 15) * 256 + threadIdx.x;
    const float* x2 = xyz2 + (size_t)b * SS * 3;
    for (int i = threadIdx.x; i < SS; i += 256) {
        float x = x2[i * 3 + 0], y = x2[i * 3 + 1], z = x2[i * 3 + 2];
        float ss = __fmaf_rn(z, z, __fmaf_rn(y, y, x * x));
        sk[i] = make_float4(-2.0f * x, -2.0f * y, -2.0f * z, ss);
    }
    __syncthreads();
    int row = b * NN + n;
    float px = xyz1[(size_t)row * 3 + 0];
    float py = xyz1[(size_t)row * 3 + 1];
    float pz = xyz1[(size_t)row * 3 + 2];
    int sv = elens[b];
    float b0 = 1e30f, b1 = 1e30f, b2 = 1e30f, b3 = 1e30f, b4 = 1e30f;
    int j0 = 0, j1 = 0, j2 = 0, j3 = 0, j4 = 0;
    for (int s = 0; s < sv; ++s) {
        float4 q = sk[s];
        float d = __fmaf_rn(px, q.x, __fmaf_rn(py, q.y, __fmaf_rn(pz, q.z, q.w)));
        if (d < b4) {
            if (d < b3) {
                b4 = b3; j4 = j3;
                if (d < b2) {
                    b3 = b2; j3 = j2;
                    if (d < b1) {
                        b2 = b1; j2 = j1;
                        if (d < b0) { b1 = b0; j1 = j0; b0 = d; j0 = s; }
                        else        { b1 = d;  j1 = s; }
                    } else { b2 = d; j2 = s; }
                } else { b3 = d; j3 = s; }
            } else { b4 = d; j4 = s; }
        }
    }
    int js[5] = { j0, j1, j2, j3, j4 };
    float rr[5];
#pragma unroll
    for (int t = 0; t < 5; ++t) {
        float4 q = sk[js[t]];
        float sx = -0.5f * q.x, sy = -0.5f * q.y, sz = -0.5f * q.z;
        float dx = px - sx, dy = py - sy, dz = pz - sz;
        float d2 = __fmaf_rn(dz, dz, __fmaf_rn(dy, dy, dx * dx));
        rr[t] = 1.0f / (d2 + EPSF);
    }
    float rsum = ((((rr[0] + rr[1]) + rr[2]) + rr[3]) + rr[4]);
    size_t base = (size_t)row * KNN;
#pragma unroll
    for (int t = 0; t < 5; ++t) {
        g_idx[base + t] = js[t];
        g_w[base + t] = rr[t] / rsum;
        out_idx[base + t] = (float)js[t];
    }
}

// ---------------- fused: blocks 0..191 small GEMM, 192..447 knn ----------
__global__ __launch_bounds__(256, 2)
void fused_knn_gemm_kernel(const float* __restrict__ xyz1,
                           const float* __restrict__ xyz2,
                           const int* __restrict__ elens,
                           float* __restrict__ out_idx,
                           const __nv_bfloat16* __restrict__ P2h,
                           const __nv_bfloat16* __restrict__ P2l,
                           const __nv_bfloat16* __restrict__ Wf0h,
                           const __nv_bfloat16* __restrict__ Wf0l,
                           float* __restrict__ Y2) {
    extern __shared__ __align__(128) char smem[];
    int bx = blockIdx.x;
    if (bx < 192) {
        gemm_body<false>(smem, bx % 3, bx / 3, P2h, P2l, Wf0h, Wf0l,
                         Y2, 12, DD2, DD2, nullptr);
    } else {
        knn_body(bx - 192, xyz1, xyz2, elens, out_idx);
    }
}

// ---------------- layer-1 GEMM kernel ----------------
__global__ __launch_bounds__(256, 2)
void gemm_mma_kernel(const __nv_bfloat16* __restrict__ Ahp,
                     const __nv_bfloat16* __restrict__ Alp,
                     const __nv_bfloat16* __restrict__ Bhp,
                     const __nv_bfloat16* __restrict__ Blp,
                     float* __restrict__ X, int nst, int lda, int ldb,
                     const int* __restrict__ plens) {
    extern __shared__ __align__(128) char smem[];
    gemm_body<true>(smem, blockIdx.x, blockIdx.y, Ahp, Alp, Bhp, Blp,
                    X, nst, lda, ldb, plens);
}

// ---------------- combine: X0 = interp(Y2) + xyz@Wxyz, fused stats -------
__global__ __launch_bounds__(256)
void combine_kernel(const float* __restrict__ points1,
                    const int* __restrict__ plens) {
    __shared__ float sW[3 * DD2];
    __shared__ float sbuf[2 * DD2];
    int tid = threadIdx.x, lane = tid & 31, wid = tid >> 5;
    int chunk = blockIdx.x;
    for (int i = tid; i < 3 * DD2; i += 256) sW[i] = g_Wxyz[i];
    for (int i = tid; i < 2 * DD2; i += 256) sbuf[i] = 0.0f;
    __syncthreads();

    int r0 = chunk * 128;
    int b = r0 >> 12;
    int lim = plens[b] - (r0 & 4095);
    int nv = lim < 0 ? 0 : (lim > 128 ? 128 : lim);
    const float* Y2b = g_Y2 + (size_t)b * SS * DD2;

#pragma unroll 1
    for (int p = 0; p < 3; ++p) {
        int colb = p * 128 + lane * 4;
        float4 wx = *(const float4*)&sW[0 * DD2 + colb];
        float4 wy = *(const float4*)&sW[1 * DD2 + colb];
        float4 wz = *(const float4*)&sW[2 * DD2 + colb];
        float s0 = 0.f, s1 = 0.f, s2c = 0.f, s3 = 0.f;
        float q0 = 0.f, q1 = 0.f, q2 = 0.f, q3 = 0.f;
#pragma unroll 1
        for (int i = 0; i < 16; ++i) {
            int r = wid + 8 * i;
            if (r >= nv) continue;
            int row = r0 + r;
            const int* ip = &g_idx[(size_t)row * KNN];
            const float* wp = &g_w[(size_t)row * KNN];
            int i0 = ip[0], i1 = ip[1], i2 = ip[2], i3 = ip[3], i4 = ip[4];
            float w0 = wp[0], w1 = wp[1], w2 = wp[2], w3 = wp[3], w4 = wp[4];
            float px = points1[(size_t)row * 3 + 0];
            float py = points1[(size_t)row * 3 + 1];
            float pz = points1[(size_t)row * 3 + 2];
            float4 y0 = *(const float4*)(Y2b + (size_t)i0 * DD2 + colb);
            float4 y1 = *(const float4*)(Y2b + (size_t)i1 * DD2 + colb);
            float4 y2 = *(const float4*)(Y2b + (size_t)i2 * DD2 + colb);
            float4 y3 = *(const float4*)(Y2b + (size_t)i3 * DD2 + colb);
            float4 y4 = *(const float4*)(Y2b + (size_t)i4 * DD2 + colb);
            float4 a;
            a.x = __fmaf_rn(pz, wz.x, __fmaf_rn(py, wy.x, px * wx.x));
            a.y = __fmaf_rn(pz, wz.y, __fmaf_rn(py, wy.y, px * wx.y));
            a.z = __fmaf_rn(pz, wz.z, __fmaf_rn(py, wy.z, px * wx.z));
            a.w = __fmaf_rn(pz, wz.w, __fmaf_rn(py, wy.w, px * wx.w));
            a.x = __fmaf_rn(w0, y0.x, a.x); a.y = __fmaf_rn(w0, y0.y, a.y);
            a.z = __fmaf_rn(w0, y0.z, a.z); a.w = __fmaf_rn(w0, y0.w, a.w);
            a.x = __fmaf_rn(w1, y1.x, a.x); a.y = __fmaf_rn(w1, y1.y, a.y);
            a.z = __fmaf_rn(w1, y1.z, a.z); a.w = __fmaf_rn(w1, y1.w, a.w);
            a.x = __fmaf_rn(w2, y2.x, a.x); a.y = __fmaf_rn(w2, y2.y, a.y);
            a.z = __fmaf_rn(w2, y2.z, a.z); a.w = __fmaf_rn(w2, y2.w, a.w);
            a.x = __fmaf_rn(w3, y3.x, a.x); a.y = __fmaf_rn(w3, y3.y, a.y);
            a.z = __fmaf_rn(w3, y3.z, a.z); a.w = __fmaf_rn(w3, y3.w, a.w);
            a.x = __fmaf_rn(w4, y4.x, a.x); a.y = __fmaf_rn(w4, y4.y, a.y);
            a.z = __fmaf_rn(w4, y4.z, a.z); a.w = __fmaf_rn(w4, y4.w, a.w);
            *(float4*)(g_X0 + (size_t)row * DD2 + colb) = a;
            s0 += a.x; q0 = __fmaf_rn(a.x, a.x, q0);
            s1 += a.y; q1 = __fmaf_rn(a.y, a.y, q1);
            s2c += a.z; q2 = __fmaf_rn(a.z, a.z, q2);
            s3 += a.w; q3 = __fmaf_rn(a.w, a.w, q3);
        }
        atomicAdd(&sbuf[colb + 0], s0); atomicAdd(&sbuf[DD2 + colb + 0], q0);
        atomicAdd(&sbuf[colb + 1], s1); atomicAdd(&sbuf[DD2 + colb + 1], q1);
        atomicAdd(&sbuf[colb + 2], s2c); atomicAdd(&sbuf[DD2 + colb + 2], q2);
        atomicAdd(&sbuf[colb + 3], s3); atomicAdd(&sbuf[DD2 + colb + 3], q3);
    }
    __syncthreads();
    for (int i = tid; i < DD2; i += 256) {
        g_part[(size_t)chunk * 768 + i] = sbuf[i];
        g_part[(size_t)chunk * 768 + DD2 + i] = sbuf[DD2 + i];
    }
}

// ---------------- finalize: mean/var -> scale/shift ----------------------
__global__ void finalize_kernel(const float* __restrict__ gamma,
                                const float* __restrict__ beta,
                                const int* __restrict__ plens, int layer) {
    int c = blockIdx.x;
    int t = threadIdx.x;
    float s = 0.0f, s2 = 0.0f;
    for (int i = t; i < 512; i += 128) {
        s  += g_part[(size_t)i * 768 + c];
        s2 += g_part[(size_t)i * 768 + 384 + c];
    }
    __shared__ float bs[128], bs2[128];
    bs[t] = s; bs2[t] = s2;
    __syncthreads();
    for (int o = 64; o > 0; o >>= 1) {
        if (t < o) { bs[t] += bs[t + o]; bs2[t] += bs2[t + o]; }
        __syncthreads();
    }
    if (t == 0) {
        float nf = 0.0f;
        for (int b = 0; b < BB; ++b) nf += (float)plens[b];
        nf = fmaxf(nf, 1.0f);
        float mean = bs[0] / nf;
        float var = bs2[0] / nf - mean * mean;
        var = fmaxf(var, 0.0f);
        float rs = rsqrtf(var + 1e-5f);
        float sc = gamma[c] * rs;
        g_scale[layer * DD2 + c] = sc;
        g_shift[layer * DD2 + c] = beta[c] - mean * sc;
    }
}

// ---------------- BN+GELU -> bf16 split activations ----------------------
__global__ void bn_gelu_split_kernel(const float* __restrict__ Xp,
                                     const int* __restrict__ plens) {
    size_t i4 = ((size_t)blockIdx.x * blockDim.x + threadIdx.x) * 4;
    if (i4 >= X_ELEMS) return;
    int row = (int)(i4 / DD2);
    int c = (int)(i4 % DD2);
    if ((row & 4095) >= plens[row >> 12]) return;
    const float* sc = g_scale + c;
    const float* sh = g_shift + c;
    float4 x = *(const float4*)(Xp + i4);
    float y0 = gelu_exact(__fmaf_rn(x.x, sc[0], sh[0]));
    float y1 = gelu_exact(__fmaf_rn(x.y, sc[1], sh[1]));
    float y2 = gelu_exact(__fmaf_rn(x.z, sc[2], sh[2]));
    float y3 = gelu_exact(__fmaf_rn(x.w, sc[3], sh[3]));
    __nv_bfloat16 h0, l0, h1, l1, h2, l2, h3, l3;
    split_bf16(y0, h0, l0); split_bf16(y1, h1, l1);
    split_bf16(y2, h2, l2); split_bf16(y3, h3, l3);
    size_t o = (size_t)row * KPAD + c;
    __nv_bfloat162* ph = (__nv_bfloat162*)(g_Ah + o);
    __nv_bfloat162* pl = (__nv_bfloat162*)(g_Al + o);
    ph[0] = __nv_bfloat162{h0, h1}; ph[1] = __nv_bfloat162{h2, h3};
    pl[0] = __nv_bfloat162{l0, l1}; pl[1] = __nv_bfloat162{l2, l3};
}

// ---------------- final masked BN (fp32, in place) -----------------------
__global__ void bn_final_kernel(float* __restrict__ Y,
                                const int* __restrict__ plens) {
    size_t i4 = ((size_t)blockIdx.x * blockDim.x + threadIdx.x) * 4;
    if (i4 >= X_ELEMS) return;
    int row = (int)(i4 / DD2);
    int c = (int)(i4 % DD2);
    bool valid = (row & 4095) < plens[row >> 12];
    float4 y;
    if (valid) {
        const float* sc = g_scale + DD2 + c;
        const float* sh = g_shift + DD2 + c;
        float4 x = *(const float4*)(Y + i4);
        y.x = __fmaf_rn(x.x, sc[0], sh[0]);
        y.y = __fmaf_rn(x.y, sc[1], sh[1]);
        y.z = __fmaf_rn(x.z, sc[2], sh[2]);
        y.w = __fmaf_rn(x.w, sc[3], sh[3]);
    } else {
        y.x = y.y = y.z = y.w = 0.0f;
    }
    *(float4*)(Y + i4) = y;
}

// ---------------- launch ----------------
extern "C" void kernel_launch(void* const* d_in, const int* in_sizes, int n_in,
                              void* d_out, int out_size) {
    const float* xyz1    = (const float*)d_in[0];
    const float* xyz2    = (const float*)d_in[1];
    const float* points1 = (const float*)d_in[2];
    const float* points2 = (const float*)d_in[3];
    const int*   plens   = (const int*)d_in[4];
    const int*   elens   = (const int*)d_in[5];
    const float* W0 = (const float*)d_in[7];
    const float* g0 = (const float*)d_in[8];
    const float* b0 = (const float*)d_in[9];
    const float* W1 = (const float*)d_in[10];
    const float* g1 = (const float*)d_in[11];
    const float* b1 = (const float*)d_in[12];
    float* out = (float*)d_out;

    __nv_bfloat16 *pAh, *pAl, *pP2h, *pP2l, *pWf0h, *pWf0l, *pW1h, *pW1l;
    float *pX0, *pY2;
    cudaGetSymbolAddress((void**)&pAh, g_Ah);
    cudaGetSymbolAddress((void**)&pAl, g_Al);
    cudaGetSymbolAddress((void**)&pX0, g_X0);
    cudaGetSymbolAddress((void**)&pY2, g_Y2);
    cudaGetSymbolAddress((void**)&pP2h, g_P2h);
    cudaGetSymbolAddress((void**)&pP2l, g_P2l);
    cudaGetSymbolAddress((void**)&pWf0h, g_Wf0h);
    cudaGetSymbolAddress((void**)&pWf0l, g_Wf0l);
    cudaGetSymbolAddress((void**)&pW1h, g_W1h);
    cudaGetSymbolAddress((void**)&pW1l, g_W1l);

    cudaFuncSetAttribute(gemm_mma_kernel,
                         cudaFuncAttributeMaxDynamicSharedMemorySize, GEMM_SMEM);
    cudaFuncSetAttribute(fused_knn_gemm_kernel,
                         cudaFuncAttributeMaxDynamicSharedMemorySize, GEMM_SMEM);

    prep_weights_kernel<<<(OC * DD2 + 255) / 256, 256>>>(W0, W1);
    prep_p2_kernel<<<(unsigned)((size_t)SROWS * DD2 / 4 + 255) / 256, 256>>>(points2);

    // fused: small GEMM (Y2 = points2 @ W0feat^T) overlapped with KNN
    fused_knn_gemm_kernel<<<448, 256, GEMM_SMEM>>>(
        xyz1, xyz2, elens, out + X_ELEMS, pP2h, pP2l, pWf0h, pWf0l, pY2);

    // combine: X0 = interp(Y2) + xyz term, fused layer-0 stats
    combine_kernel<<<512, 256>>>(points1, plens);
    finalize_kernel<<<384, 128>>>(g0, b0, plens, 0);
    bn_gelu_split_kernel<<<(unsigned)(X_ELEMS / 4 + 255) / 256, 256>>>(pX0, plens);

    // layer 1: out = act @ W1^T  (K = 384), stats fused, masked-chunk skip
    gemm_mma_kernel<<<dim3(3, MM / 128), 256, GEMM_SMEM>>>(
        pAh, pAl, pW1h, pW1l, out, 12, KPAD, DD2, plens);
    finalize_kernel<<<384, 128>>>(g1, b1, plens, 1);
    bn_final_kernel<<<(unsigned)(X_ELEMS / 4 + 255) / 256, 256>>>(out, plens);
}

// round 16
// speedup vs baseline: 2.0463x; 1.0258x over previous
#include <cuda_runtime.h>
#include <cuda_bf16.h>
#include <math.h>
#include <stdint.h>

// ---------------- problem constants ----------------
#define BB   16
#define NN   4096
#define SS   512
#define DD2  384
#define KNN  5
#define MM   (BB*NN)          // 65536 rows
#define SROWS (BB*SS)         // 8192 rows of points2
#define KPAD 416              // stride for activation bf16 arrays (gemm1 A)
#define OC   384              // output channels
#define X_ELEMS ((size_t)MM*DD2)   // 25165824
#define EPSF 1.1920929e-7f

// Layer-0 restructuring (linearity): X0 = sum_k w_k * Y2[idx_k] + xyz @ W0xyz^T
// where Y2 = points2 @ W0feat^T is computed over only 8192 rows.
// R15: knn + small GEMM fused into one block-specialized launch.
// R16: combine split over column blocks (grid 3x512) to fix its latency-bound
// occupancy (ncu: 59.8us, occ 32%, issue 23%, no pipe >40%).

// ---------------- device scratch (static, no allocation) ----------------
__device__ __align__(128) __nv_bfloat16 g_Ah[(size_t)MM * KPAD];   // gemm1 A hi
__device__ __align__(128) __nv_bfloat16 g_Al[(size_t)MM * KPAD];   // gemm1 A lo
__device__ __align__(128) float g_X0[(size_t)MM * DD2];
__device__ __align__(128) float g_Y2[(size_t)SROWS * DD2];
__device__ __align__(128) __nv_bfloat16 g_P2h[(size_t)SROWS * DD2];
__device__ __align__(128) __nv_bfloat16 g_P2l[(size_t)SROWS * DD2];
__device__ __align__(128) __nv_bfloat16 g_Wf0h[OC * DD2];
__device__ __align__(128) __nv_bfloat16 g_Wf0l[OC * DD2];
__device__ __align__(128) __nv_bfloat16 g_W1h[OC * DD2];
__device__ __align__(128) __nv_bfloat16 g_W1l[OC * DD2];
__device__ __align__(128) float g_Wxyz[3 * DD2];   // [j][o] transposed
__device__ int   g_idx[MM * KNN];
__device__ float g_w[MM * KNN];
__device__ float g_part[512 * 2 * DD2];
__device__ float g_scale[2 * DD2];
__device__ float g_shift[2 * DD2];

// ---------------- helpers ----------------
__device__ __forceinline__ uint32_t smem_u32(const void* p) {
    uint32_t a;
    asm("{ .reg .u64 t; cvta.to.shared.u64 t, %1; cvt.u32.u64 %0, t; }" : "=r"(a) : "l"(p));
    return a;
}
__device__ __forceinline__ void cp16(uint32_t s, const void* g) {
    asm volatile("cp.async.cg.shared.global [%0], [%1], 16;" :: "r"(s), "l"(g));
}
#define CP_COMMIT() asm volatile("cp.async.commit_group;")
#define CP_WAIT1()  asm volatile("cp.async.wait_group 1;")
#define CP_WAIT0()  asm volatile("cp.async.wait_group 0;")

#define LDSM4(r, addr) \
    asm volatile("ldmatrix.sync.aligned.m8n8.x4.shared.b16 {%0,%1,%2,%3}, [%4];" \
        : "=r"((r)[0]), "=r"((r)[1]), "=r"((r)[2]), "=r"((r)[3]) : "r"(addr))

__device__ __forceinline__ void mma16816(float* c, const uint32_t* a, const uint32_t* b) {
    asm volatile(
        "mma.sync.aligned.m16n8k16.row.col.f32.bf16.bf16.f32 "
        "{%0,%1,%2,%3}, {%4,%5,%6,%7}, {%8,%9}, {%0,%1,%2,%3};"
        : "+f"(c[0]), "+f"(c[1]), "+f"(c[2]), "+f"(c[3])
        : "r"(a[0]), "r"(a[1]), "r"(a[2]), "r"(a[3]), "r"(b[0]), "r"(b[1]));
}

__device__ __forceinline__ float gelu_exact(float v) {
    return 0.5f * v * (1.0f + erff(v * 0.7071067811865476f));
}
__device__ __forceinline__ void split_bf16(float v, __nv_bfloat16 &h, __nv_bfloat16 &l) {
    h = __float2bfloat16(v);
    l = __float2bfloat16(v - __bfloat162float(h));
}

// ---------------- weight prep ----------------
__global__ void prep_weights_kernel(const float* __restrict__ W0,
                                    const float* __restrict__ W1) {
    int i = blockIdx.x * blockDim.x + threadIdx.x;
    if (i >= OC * DD2) return;
    int o = i / DD2, k = i % DD2;
    __nv_bfloat16 h, l;
    split_bf16(W0[o * 387 + 3 + k], h, l); g_Wf0h[i] = h; g_Wf0l[i] = l;
    split_bf16(W1[o * DD2 + k], h, l);     g_W1h[i] = h; g_W1l[i] = l;
    if (i < 3 * DD2) {
        int j = i / DD2, o2 = i % DD2;
        g_Wxyz[i] = W0[o2 * 387 + j];
    }
}

// ---------------- points2 bf16 split ----------------
__global__ void prep_p2_kernel(const float* __restrict__ points2) {
    size_t i4 = ((size_t)blockIdx.x * blockDim.x + threadIdx.x) * 4;
    if (i4 >= (size_t)SROWS * DD2) return;
    float4 v = *(const float4*)(points2 + i4);
    __nv_bfloat16 h0, l0, h1, l1, h2, l2, h3, l3;
    split_bf16(v.x, h0, l0); split_bf16(v.y, h1, l1);
    split_bf16(v.z, h2, l2); split_bf16(v.w, h3, l3);
    __nv_bfloat162* ph = (__nv_bfloat162*)(g_P2h + i4);
    __nv_bfloat162* pl = (__nv_bfloat162*)(g_P2l + i4);
    ph[0] = __nv_bfloat162{h0, h1}; ph[1] = __nv_bfloat162{h2, h3};
    pl[0] = __nv_bfloat162{l0, l1}; pl[1] = __nv_bfloat162{l2, l3};
}

// ---------------- GEMM body (shared by small gemm and layer-1 gemm) ------
// C[128 rows, 128 cols tile] = A[.,K] * B^T.  warp 64x32, KC=32, 2 stages.
#define STAGE_SZ 32768
#define GEMM_SMEM (2*STAGE_SZ)

template <bool STATS>
__device__ __forceinline__ void gemm_body(
    char* smem, int bxn, int by,
    const __nv_bfloat16* __restrict__ Ahp, const __nv_bfloat16* __restrict__ Alp,
    const __nv_bfloat16* __restrict__ Bhp, const __nv_bfloat16* __restrict__ Blp,
    float* __restrict__ X, int nst, int lda, int ldb,
    const int* __restrict__ plens) {
    uint32_t sb = smem_u32(smem);
    int tid = threadIdx.x, lane = tid & 31, wid = tid >> 5;
    int wm = wid & 1, wn = wid >> 1;
    int mbase = by * 128, nbase = bxn * 128;
    int chunk = by;

    int nv = 128;
    if (STATS) {
        int bidx = mbase >> 12;
        int lim = plens[bidx] - (mbase & 4095);
        if (lim <= 0) {
            if (tid < 128)       g_part[(size_t)chunk * 768 + nbase + tid] = 0.0f;
            else                 g_part[(size_t)chunk * 768 + 384 + nbase + (tid - 128)] = 0.0f;
            return;
        }
        nv = lim > 128 ? 128 : lim;
    }

    int lrow = tid >> 2, lc = tid & 3;

    auto load_stage = [&](int st) {
        uint32_t sA = sb + (st & 1) * STAGE_SZ;
        int kb = st * 32;
#pragma unroll
        for (int i = 0; i < 2; ++i) {
            int row = lrow + i * 64;
            uint32_t so = row * 64 + ((uint32_t)(lc ^ ((row >> 1) & 3)) << 4);
            size_t ga = (size_t)(mbase + row) * lda + kb + lc * 8;
            size_t gb = (size_t)(nbase + row) * ldb + kb + lc * 8;
            cp16(sA + so,         Ahp + ga);
            cp16(sA + 8192 + so,  Alp + ga);
            cp16(sA + 16384 + so, Bhp + gb);
            cp16(sA + 24576 + so, Blp + gb);
        }
    };

    float acc[4][4][4] = {};

    load_stage(0); CP_COMMIT();

    int arow = lane & 15;
    int ahalf = lane >> 4;
    int brow = (lane & 7) + ((lane >> 4) << 3);
    int bhalf = (lane >> 3) & 1;

    for (int st = 0; st < nst; ++st) {
        if (st + 1 < nst) { load_stage(st + 1); CP_COMMIT(); CP_WAIT1(); }
        else              { CP_WAIT0(); }
        __syncthreads();
        uint32_t sA = sb + (st & 1) * STAGE_SZ;
        uint32_t sAl = sA + 8192, sB = sA + 16384, sBl = sA + 24576;
#pragma unroll
        for (int k2 = 0; k2 < 2; ++k2) {
            int cbase = 2 * k2;
            uint32_t ah[4][4], bh[2][4], bl[2][4];
            uint32_t aso[4], bso[2];
#pragma unroll
            for (int mi = 0; mi < 4; ++mi) {
                int row = wm * 64 + mi * 16 + arow;
                aso[mi] = row * 64 + ((uint32_t)((cbase + ahalf) ^ ((row >> 1) & 3)) << 4);
                LDSM4(ah[mi], sA + aso[mi]);
            }
#pragma unroll
            for (int g = 0; g < 2; ++g) {
                int row = wn * 32 + g * 16 + brow;
                bso[g] = row * 64 + ((uint32_t)((cbase + bhalf) ^ ((row >> 1) & 3)) << 4);
                LDSM4(bh[g], sB + bso[g]);
            }
#pragma unroll
            for (int mi = 0; mi < 4; ++mi)
#pragma unroll
                for (int ni = 0; ni < 4; ++ni)
                    mma16816(acc[mi][ni], ah[mi], &bh[ni >> 1][(ni & 1) * 2]);
#pragma unroll
            for (int g = 0; g < 2; ++g) LDSM4(bl[g], sBl + bso[g]);
#pragma unroll
            for (int mi = 0; mi < 4; ++mi)
#pragma unroll
                for (int ni = 0; ni < 4; ++ni)
                    mma16816(acc[mi][ni], ah[mi], &bl[ni >> 1][(ni & 1) * 2]);
#pragma unroll
            for (int mi = 0; mi < 4; ++mi) LDSM4(ah[mi], sAl + aso[mi]);
#pragma unroll
            for (int mi = 0; mi < 4; ++mi)
#pragma unroll
                for (int ni = 0; ni < 4; ++ni)
                    mma16816(acc[mi][ni], ah[mi], &bh[ni >> 1][(ni & 1) * 2]);
        }
        __syncthreads();
    }

    // ---- output store ----
    int row0 = mbase + wm * 64 + (lane >> 2);
    int col0 = nbase + wn * 32 + 2 * (lane & 3);
#pragma unroll
    for (int mi = 0; mi < 4; ++mi) {
#pragma unroll
        for (int ni = 0; ni < 4; ++ni) {
            int r = row0 + mi * 16;
            int c = col0 + ni * 8;
            float2 v;
            v.x = acc[mi][ni][0]; v.y = acc[mi][ni][1];
            *(float2*)(X + (size_t)r * OC + c) = v;
            v.x = acc[mi][ni][2]; v.y = acc[mi][ni][3];
            *(float2*)(X + (size_t)(r + 8) * OC + c) = v;
        }
    }

    if (!STATS) return;

    // ---- fused masked stats ----
    float* sbuf = (float*)smem;
    __syncthreads();
    sbuf[tid] = 0.0f;
    __syncthreads();

    int ritb = wm * 64 + (lane >> 2);
    float csum[8], csq[8];
#pragma unroll
    for (int t = 0; t < 8; ++t) { csum[t] = 0.0f; csq[t] = 0.0f; }
#pragma unroll
    for (int mi = 0; mi < 4; ++mi) {
#pragma unroll
        for (int j = 0; j < 2; ++j) {
            bool v = (ritb + mi * 16 + 8 * j) < nv;
            if (v) {
#pragma unroll
                for (int ni = 0; ni < 4; ++ni) {
                    float a0 = acc[mi][ni][2 * j + 0];
                    float a1 = acc[mi][ni][2 * j + 1];
                    csum[2 * ni + 0] += a0;
                    csq[2 * ni + 0] = __fmaf_rn(a0, a0, csq[2 * ni + 0]);
                    csum[2 * ni + 1] += a1;
                    csq[2 * ni + 1] = __fmaf_rn(a1, a1, csq[2 * ni + 1]);
                }
            }
        }
    }
#pragma unroll
    for (int m = 4; m <= 16; m <<= 1) {
#pragma unroll
        for (int t = 0; t < 8; ++t) {
            csum[t] += __shfl_xor_sync(0xFFFFFFFFu, csum[t], m);
            csq[t]  += __shfl_xor_sync(0xFFFFFFFFu, csq[t], m);
        }
    }
    if (lane < 4) {
#pragma unroll
        for (int ni = 0; ni < 4; ++ni) {
#pragma unroll
            for (int j = 0; j < 2; ++j) {
                int col = wn * 32 + ni * 8 + 2 * lane + j;
                atomicAdd(&sbuf[col], csum[2 * ni + j]);
                atomicAdd(&sbuf[128 + col], csq[2 * ni + j]);
            }
        }
    }
    __syncthreads();
    if (tid < 128)       g_part[(size_t)chunk * 768 + nbase + tid] = sbuf[tid];
    else                 g_part[(size_t)chunk * 768 + 384 + nbase + (tid - 128)] = sbuf[tid];
}

// ---------------- KNN body (3-FFMA comparison key) ----------------
__device__ __forceinline__ void knn_body(
    int kb, const float* __restrict__ xyz1, const float* __restrict__ xyz2,
    const int* __restrict__ elens, float* __restrict__ out_idx) {
    __shared__ float4 sk[SS];
    int b = kb >> 4;
    int n = (kb & 15) * 256 + threadIdx.x;
    const float* x2 = xyz2 + (size_t)b * SS * 3;
    for (int i = threadIdx.x; i < SS; i += 256) {
        float x = x2[i * 3 + 0], y = x2[i * 3 + 1], z = x2[i * 3 + 2];
        float ss = __fmaf_rn(z, z, __fmaf_rn(y, y, x * x));
        sk[i] = make_float4(-2.0f * x, -2.0f * y, -2.0f * z, ss);
    }
    __syncthreads();
    int row = b * NN + n;
    float px = xyz1[(size_t)row * 3 + 0];
    float py = xyz1[(size_t)row * 3 + 1];
    float pz = xyz1[(size_t)row * 3 + 2];
    int sv = elens[b];
    float b0 = 1e30f, b1 = 1e30f, b2 = 1e30f, b3 = 1e30f, b4 = 1e30f;
    int j0 = 0, j1 = 0, j2 = 0, j3 = 0, j4 = 0;
    for (int s = 0; s < sv; ++s) {
        float4 q = sk[s];
        float d = __fmaf_rn(px, q.x, __fmaf_rn(py, q.y, __fmaf_rn(pz, q.z, q.w)));
        if (d < b4) {
            if (d < b3) {
                b4 = b3; j4 = j3;
                if (d < b2) {
                    b3 = b2; j3 = j2;
                    if (d < b1) {
                        b2 = b1; j2 = j1;
                        if (d < b0) { b1 = b0; j1 = j0; b0 = d; j0 = s; }
                        else        { b1 = d;  j1 = s; }
                    } else { b2 = d; j2 = s; }
                } else { b3 = d; j3 = s; }
            } else { b4 = d; j4 = s; }
        }
    }
    int js[5] = { j0, j1, j2, j3, j4 };
    float rr[5];
#pragma unroll
    for (int t = 0; t < 5; ++t) {
        float4 q = sk[js[t]];
        float sx = -0.5f * q.x, sy = -0.5f * q.y, sz = -0.5f * q.z;
        float dx = px - sx, dy = py - sy, dz = pz - sz;
        float d2 = __fmaf_rn(dz, dz, __fmaf_rn(dy, dy, dx * dx));
        rr[t] = 1.0f / (d2 + EPSF);
    }
    float rsum = ((((rr[0] + rr[1]) + rr[2]) + rr[3]) + rr[4]);
    size_t base = (size_t)row * KNN;
#pragma unroll
    for (int t = 0; t < 5; ++t) {
        g_idx[base + t] = js[t];
        g_w[base + t] = rr[t] / rsum;
        out_idx[base + t] = (float)js[t];
    }
}

// ---------------- fused: blocks 0..191 small GEMM, 192..447 knn ----------
__global__ __launch_bounds__(256, 2)
void fused_knn_gemm_kernel(const float* __restrict__ xyz1,
                           const float* __restrict__ xyz2,
                           const int* __restrict__ elens,
                           float* __restrict__ out_idx,
                           const __nv_bfloat16* __restrict__ P2h,
                           const __nv_bfloat16* __restrict__ P2l,
                           const __nv_bfloat16* __restrict__ Wf0h,
                           const __nv_bfloat16* __restrict__ Wf0l,
                           float* __restrict__ Y2) {
    extern __shared__ __align__(128) char smem[];
    int bx = blockIdx.x;
    if (bx < 192) {
        gemm_body<false>(smem, bx % 3, bx / 3, P2h, P2l, Wf0h, Wf0l,
                         Y2, 12, DD2, DD2, nullptr);
    } else {
        knn_body(bx - 192, xyz1, xyz2, elens, out_idx);
    }
}

// ---------------- layer-1 GEMM kernel ----------------
__global__ __launch_bounds__(256, 2)
void gemm_mma_kernel(const __nv_bfloat16* __restrict__ Ahp,
                     const __nv_bfloat16* __restrict__ Alp,
                     const __nv_bfloat16* __restrict__ Bhp,
                     const __nv_bfloat16* __restrict__ Blp,
                     float* __restrict__ X, int nst, int lda, int ldb,
                     const int* __restrict__ plens) {
    extern __shared__ __align__(128) char smem[];
    gemm_body<true>(smem, blockIdx.x, blockIdx.y, Ahp, Alp, Bhp, Blp,
                    X, nst, lda, ldb, plens);
}

// ---------------- combine: X0 = interp(Y2) + xyz@Wxyz, fused stats -------
// R16: grid (3 col-blocks, 512 chunks) for 3x the concurrency of the
// latency-bound gather loop. Each block covers 128 rows x 128 cols.
__global__ __launch_bounds__(256)
void combine_kernel(const float* __restrict__ points1,
                    const int* __restrict__ plens) {
    __shared__ float sW[3 * 128];    // Wxyz slice for this col block
    __shared__ float sbuf[2 * 128];  // per-(chunk, colblock) stats
    int tid = threadIdx.x, lane = tid & 31, wid = tid >> 5;
    int p = blockIdx.x;              // col block 0..2
    int chunk = blockIdx.y;          // 0..511
    int cb0 = p * 128;
    for (int i = tid; i < 3 * 128; i += 256) {
        int j = i >> 7, c = i & 127;
        sW[i] = g_Wxyz[j * DD2 + cb0 + c];
    }
    if (tid < 256) { sbuf[tid] = 0.0f; }
    __syncthreads();

    int r0 = chunk * 128;
    int b = r0 >> 12;
    int lim = plens[b] - (r0 & 4095);
    int nv = lim < 0 ? 0 : (lim > 128 ? 128 : lim);
    const float* Y2b = g_Y2 + (size_t)b * SS * DD2 + cb0;

    int cl = lane * 4;   // col within block
    float4 wx = *(const float4*)&sW[0 * 128 + cl];
    float4 wy = *(const float4*)&sW[1 * 128 + cl];
    float4 wz = *(const float4*)&sW[2 * 128 + cl];
    float s0 = 0.f, s1 = 0.f, s2c = 0.f, s3 = 0.f;
    float q0 = 0.f, q1 = 0.f, q2 = 0.f, q3 = 0.f;
#pragma unroll 1
    for (int i = 0; i < 16; ++i) {
        int r = wid + 8 * i;
        if (r >= nv) continue;
        int row = r0 + r;
        const int* ip = &g_idx[(size_t)row * KNN];
        const float* wp = &g_w[(size_t)row * KNN];
        int i0 = ip[0], i1 = ip[1], i2 = ip[2], i3 = ip[3], i4 = ip[4];
        float w0 = wp[0], w1 = wp[1], w2 = wp[2], w3 = wp[3], w4 = wp[4];
        float px = points1[(size_t)row * 3 + 0];
        float py = points1[(size_t)row * 3 + 1];
        float pz = points1[(size_t)row * 3 + 2];
        float4 y0 = *(const float4*)(Y2b + (size_t)i0 * DD2 + cl);
        float4 y1 = *(const float4*)(Y2b + (size_t)i1 * DD2 + cl);
        float4 y2 = *(const float4*)(Y2b + (size_t)i2 * DD2 + cl);
        float4 y3 = *(const float4*)(Y2b + (size_t)i3 * DD2 + cl);
        float4 y4 = *(const float4*)(Y2b + (size_t)i4 * DD2 + cl);
        float4 a;
        a.x = __fmaf_rn(pz, wz.x, __fmaf_rn(py, wy.x, px * wx.x));
        a.y = __fmaf_rn(pz, wz.y, __fmaf_rn(py, wy.y, px * wx.y));
        a.z = __fmaf_rn(pz, wz.z, __fmaf_rn(py, wy.z, px * wx.z));
        a.w = __fmaf_rn(pz, wz.w, __fmaf_rn(py, wy.w, px * wx.w));
        a.x = __fmaf_rn(w0, y0.x, a.x); a.y = __fmaf_rn(w0, y0.y, a.y);
        a.z = __fmaf_rn(w0, y0.z, a.z); a.w = __fmaf_rn(w0, y0.w, a.w);
        a.x = __fmaf_rn(w1, y1.x, a.x); a.y = __fmaf_rn(w1, y1.y, a.y);
        a.z = __fmaf_rn(w1, y1.z, a.z); a.w = __fmaf_rn(w1, y1.w, a.w);
        a.x = __fmaf_rn(w2, y2.x, a.x); a.y = __fmaf_rn(w2, y2.y, a.y);
        a.z = __fmaf_rn(w2, y2.z, a.z); a.w = __fmaf_rn(w2, y2.w, a.w);
        a.x = __fmaf_rn(w3, y3.x, a.x); a.y = __fmaf_rn(w3, y3.y, a.y);
        a.z = __fmaf_rn(w3, y3.z, a.z); a.w = __fmaf_rn(w3, y3.w, a.w);
        a.x = __fmaf_rn(w4, y4.x, a.x); a.y = __fmaf_rn(w4, y4.y, a.y);
        a.z = __fmaf_rn(w4, y4.z, a.z); a.w = __fmaf_rn(w4, y4.w, a.w);
        *(float4*)(g_X0 + (size_t)row * DD2 + cb0 + cl) = a;
        s0 += a.x; q0 = __fmaf_rn(a.x, a.x, q0);
        s1 += a.y; q1 = __fmaf_rn(a.y, a.y, q1);
        s2c += a.z; q2 = __fmaf_rn(a.z, a.z, q2);
        s3 += a.w; q3 = __fmaf_rn(a.w, a.w, q3);
    }
    atomicAdd(&sbuf[cl + 0], s0); atomicAdd(&sbuf[128 + cl + 0], q0);
    atomicAdd(&sbuf[cl + 1], s1); atomicAdd(&sbuf[128 + cl + 1], q1);
    atomicAdd(&sbuf[cl + 2], s2c); atomicAdd(&sbuf[128 + cl + 2], q2);
    atomicAdd(&sbuf[cl + 3], s3); atomicAdd(&sbuf[128 + cl + 3], q3);
    __syncthreads();
    if (tid < 128)       g_part[(size_t)chunk * 768 + cb0 + tid] = sbuf[tid];
    else                 g_part[(size_t)chunk * 768 + 384 + cb0 + (tid - 128)] = sbuf[tid];
}

// ---------------- finalize: mean/var -> scale/shift ----------------------
__global__ void finalize_kernel(const float* __restrict__ gamma,
                                const float* __restrict__ beta,
                                const int* __restrict__ plens, int layer) {
    int c = blockIdx.x;
    int t = threadIdx.x;
    float s = 0.0f, s2 = 0.0f;
    for (int i = t; i < 512; i += 128) {
        s  += g_part[(size_t)i * 768 + c];
        s2 += g_part[(size_t)i * 768 + 384 + c];
    }
    __shared__ float bs[128], bs2[128];
    bs[t] = s; bs2[t] = s2;
    __syncthreads();
    for (int o = 64; o > 0; o >>= 1) {
        if (t < o) { bs[t] += bs[t + o]; bs2[t] += bs2[t + o]; }
        __syncthreads();
    }
    if (t == 0) {
        float nf = 0.0f;
        for (int b = 0; b < BB; ++b) nf += (float)plens[b];
        nf = fmaxf(nf, 1.0f);
        float mean = bs[0] / nf;
        float var = bs2[0] / nf - mean * mean;
        var = fmaxf(var, 0.0f);
        float rs = rsqrtf(var + 1e-5f);
        float sc = gamma[c] * rs;
        g_scale[layer * DD2 + c] = sc;
        g_shift[layer * DD2 + c] = beta[c] - mean * sc;
    }
}

// ---------------- BN+GELU -> bf16 split activations ----------------------
__global__ void bn_gelu_split_kernel(const float* __restrict__ Xp,
                                     const int* __restrict__ plens) {
    size_t i4 = ((size_t)blockIdx.x * blockDim.x + threadIdx.x) * 4;
    if (i4 >= X_ELEMS) return;
    int row = (int)(i4 / DD2);
    int c = (int)(i4 % DD2);
    if ((row & 4095) >= plens[row >> 12]) return;
    const float* sc = g_scale + c;
    const float* sh = g_shift + c;
    float4 x = *(const float4*)(Xp + i4);
    float y0 = gelu_exact(__fmaf_rn(x.x, sc[0], sh[0]));
    float y1 = gelu_exact(__fmaf_rn(x.y, sc[1], sh[1]));
    float y2 = gelu_exact(__fmaf_rn(x.z, sc[2], sh[2]));
    float y3 = gelu_exact(__fmaf_rn(x.w, sc[3], sh[3]));
    __nv_bfloat16 h0, l0, h1, l1, h2, l2, h3, l3;
    split_bf16(y0, h0, l0); split_bf16(y1, h1, l1);
    split_bf16(y2, h2, l2); split_bf16(y3, h3, l3);
    size_t o = (size_t)row * KPAD + c;
    __nv_bfloat162* ph = (__nv_bfloat162*)(g_Ah + o);
    __nv_bfloat162* pl = (__nv_bfloat162*)(g_Al + o);
    ph[0] = __nv_bfloat162{h0, h1}; ph[1] = __nv_bfloat162{h2, h3};
    pl[0] = __nv_bfloat162{l0, l1}; pl[1] = __nv_bfloat162{l2, l3};
}

// ---------------- final masked BN (fp32, in place) -----------------------
__global__ void bn_final_kernel(float* __restrict__ Y,
                                const int* __restrict__ plens) {
    size_t i4 = ((size_t)blockIdx.x * blockDim.x + threadIdx.x) * 4;
    if (i4 >= X_ELEMS) return;
    int row = (int)(i4 / DD2);
    int c = (int)(i4 % DD2);
    bool valid = (row & 4095) < plens[row >> 12];
    float4 y;
    if (valid) {
        const float* sc = g_scale + DD2 + c;
        const float* sh = g_shift + DD2 + c;
        float4 x = *(const float4*)(Y + i4);
        y.x = __fmaf_rn(x.x, sc[0], sh[0]);
        y.y = __fmaf_rn(x.y, sc[1], sh[1]);
        y.z = __fmaf_rn(x.z, sc[2], sh[2]);
        y.w = __fmaf_rn(x.w, sc[3], sh[3]);
    } else {
        y.x = y.y = y.z = y.w = 0.0f;
    }
    *(float4*)(Y + i4) = y;
}

// ---------------- launch ----------------
extern "C" void kernel_launch(void* const* d_in, const int* in_sizes, int n_in,
                              void* d_out, int out_size) {
    const float* xyz1    = (const float*)d_in[0];
    const float* xyz2    = (const float*)d_in[1];
    const float* points1 = (const float*)d_in[2];
    const float* points2 = (const float*)d_in[3];
    const int*   plens   = (const int*)d_in[4];
    const int*   elens   = (const int*)d_in[5];
    const float* W0 = (const float*)d_in[7];
    const float* g0 = (const float*)d_in[8];
    const float* b0 = (const float*)d_in[9];
    const float* W1 = (const float*)d_in[10];
    const float* g1 = (const float*)d_in[11];
    const float* b1 = (const float*)d_in[12];
    float* out = (float*)d_out;

    __nv_bfloat16 *pAh, *pAl, *pP2h, *pP2l, *pWf0h, *pWf0l, *pW1h, *pW1l;
    float *pX0, *pY2;
    cudaGetSymbolAddress((void**)&pAh, g_Ah);
    cudaGetSymbolAddress((void**)&pAl, g_Al);
    cudaGetSymbolAddress((void**)&pX0, g_X0);
    cudaGetSymbolAddress((void**)&pY2, g_Y2);
    cudaGetSymbolAddress((void**)&pP2h, g_P2h);
    cudaGetSymbolAddress((void**)&pP2l, g_P2l);
    cudaGetSymbolAddress((void**)&pWf0h, g_Wf0h);
    cudaGetSymbolAddress((void**)&pWf0l, g_Wf0l);
    cudaGetSymbolAddress((void**)&pW1h, g_W1h);
    cudaGetSymbolAddress((void**)&pW1l, g_W1l);

    cudaFuncSetAttribute(gemm_mma_kernel,
                         cudaFuncAttributeMaxDynamicSharedMemorySize, GEMM_SMEM);
    cudaFuncSetAttribute(fused_knn_gemm_kernel,
                         cudaFuncAttributeMaxDynamicSharedMemorySize, GEMM_SMEM);

    prep_weights_kernel<<<(OC * DD2 + 255) / 256, 256>>>(W0, W1);
    prep_p2_kernel<<<(unsigned)((size_t)SROWS * DD2 / 4 + 255) / 256, 256>>>(points2);

    // fused: small GEMM (Y2 = points2 @ W0feat^T) overlapped with KNN
    fused_knn_gemm_kernel<<<448, 256, GEMM_SMEM>>>(
        xyz1, xyz2, elens, out + X_ELEMS, pP2h, pP2l, pWf0h, pWf0l, pY2);

    // combine: X0 = interp(Y2) + xyz term, fused layer-0 stats (3 col blocks)
    combine_kernel<<<dim3(3, 512), 256>>>(points1, plens);
    finalize_kernel<<<384, 128>>>(g0, b0, plens, 0);
    bn_gelu_split_kernel<<<(unsigned)(X_ELEMS / 4 + 255) / 256, 256>>>(pX0, plens);

    // layer 1: out = act @ W1^T  (K = 384), stats fused, masked-chunk skip
    gemm_mma_kernel<<<dim3(3, MM / 128), 256, GEMM_SMEM>>>(
        pAh, pAl, pW1h, pW1l, out, 12, KPAD, DD2, plens);
    finalize_kernel<<<384, 128>>>(g1, b1, plens, 1);
    bn_final_kernel<<<(unsigned)(X_ELEMS / 4 + 255) / 256, 256>>>(out, plens);
}